// round 6
// baseline (speedup 1.0000x reference)
#include <cuda_runtime.h>
#include <cuda_fp16.h>
#include <cstdint>

#define Bz 8
#define Ns 2048
#define Ms 2048
#define Dd 1024
#define Hh 1024
#define Oo 1024

#define BM 128
#define BN 256
#define BK 32
#define LDS 40        // padded row stride in halves (80B, conflict-free ldmatrix)
#define NSTAGE 3
#define TILE_A (BM * LDS)   // halves
#define TILE_B (BN * LDS)   // halves

// ---------------- device scratch ----------------
__device__ __half g_h1h[Bz * Ns * Dd];
__device__ __half g_h1l[Bz * Ns * Dd];
__device__ __half g_h2h[Bz * Ms * Dd];
__device__ __half g_h2l[Bz * Ms * Dd];
__device__ __half g_Wqh[Hh * Dd];
__device__ __half g_Wql[Hh * Dd];
__device__ __half g_Wkh[Hh * Dd];
__device__ __half g_Wkl[Hh * Dd];
__device__ __half g_Wvh[Oo * Dd];
__device__ __half g_Wvl[Oo * Dd];
__device__ __half g_Qh[Bz * Ns * Hh];
__device__ __half g_Ql[Bz * Ns * Hh];
__device__ __half g_Kh[Bz * Ms * Hh];
__device__ __half g_Kl[Bz * Ms * Hh];
__device__ __half g_Vth[Bz * Oo * Ms];   // V transposed: [b][o][m]
__device__ __half g_Vtl[Bz * Oo * Ms];
__device__ float  g_E[(size_t)Bz * Ns * Ms];
__device__ __half g_P[(size_t)Bz * Ns * Ms];

// ---------------- fused fp32 -> fp16 hi/lo split ----------------
#define R0 4194304
#define R1 8388608
#define R2q 8650752
#define R3k 8912896
#define R4v 9175040

__global__ void split_all_kernel(const float4* __restrict__ h1, const float4* __restrict__ h2,
                                 const float4* __restrict__ Wq, const float4* __restrict__ Wk,
                                 const float4* __restrict__ Wv,
                                 __half2* __restrict__ h1h, __half2* __restrict__ h1l,
                                 __half2* __restrict__ h2h, __half2* __restrict__ h2l,
                                 __half2* __restrict__ Wqh, __half2* __restrict__ Wql,
                                 __half2* __restrict__ Wkh, __half2* __restrict__ Wkl,
                                 __half2* __restrict__ Wvh, __half2* __restrict__ Wvl) {
    int i = blockIdx.x * blockDim.x + threadIdx.x;
    const float4* src;
    __half2 *hi, *lo;
    int j;
    if (i < R0)       { src = h1; hi = h1h; lo = h1l; j = i; }
    else if (i < R1)  { src = h2; hi = h2h; lo = h2l; j = i - R0; }
    else if (i < R2q) { src = Wq; hi = Wqh; lo = Wql; j = i - R1; }
    else if (i < R3k) { src = Wk; hi = Wkh; lo = Wkl; j = i - R2q; }
    else if (i < R4v) { src = Wv; hi = Wvh; lo = Wvl; j = i - R3k; }
    else return;
    float4 v = src[j];
    __half a = __float2half_rn(v.x), b = __float2half_rn(v.y);
    __half c = __float2half_rn(v.z), d = __float2half_rn(v.w);
    hi[2 * j + 0] = __halves2half2(a, b);
    hi[2 * j + 1] = __halves2half2(c, d);
    lo[2 * j + 0] = __halves2half2(__float2half_rn(v.x - __half2float(a)),
                                   __float2half_rn(v.y - __half2float(b)));
    lo[2 * j + 1] = __halves2half2(__float2half_rn(v.z - __half2float(c)),
                                   __float2half_rn(v.w - __half2float(d)));
}

// ---------------- PTX helpers ----------------
__device__ __forceinline__ void ldsm4(uint32_t& r0, uint32_t& r1, uint32_t& r2, uint32_t& r3,
                                      uint32_t addr) {
    asm volatile("ldmatrix.sync.aligned.m8n8.x4.shared.b16 {%0,%1,%2,%3}, [%4];"
                 : "=r"(r0), "=r"(r1), "=r"(r2), "=r"(r3)
                 : "r"(addr));
}

__device__ __forceinline__ void mma16816(float* c, const uint32_t* a, uint32_t b0, uint32_t b1) {
    asm volatile("mma.sync.aligned.m16n8k16.row.col.f32.f16.f16.f32 "
                 "{%0,%1,%2,%3}, {%4,%5,%6,%7}, {%8,%9}, {%0,%1,%2,%3};"
                 : "+f"(c[0]), "+f"(c[1]), "+f"(c[2]), "+f"(c[3])
                 : "r"(a[0]), "r"(a[1]), "r"(a[2]), "r"(a[3]), "r"(b0), "r"(b1));
}

__device__ __forceinline__ void cp16(uint32_t dst, const void* src) {
    asm volatile("cp.async.cg.shared.global [%0], [%1], 16;" :: "r"(dst), "l"(src));
}
__device__ __forceinline__ void cp_commit() { asm volatile("cp.async.commit_group;"); }
template <int N>
__device__ __forceinline__ void cp_wait() { asm volatile("cp.async.wait_group %0;" :: "n"(N)); }

// ---------------- pipelined split GEMM, 64x64 warp tiles ----------------
// C = Ah*Bh^T + Ah*Bl^T (+ Al*Bh^T if NT==3)
// A: [Mdim x K] row-major, B: [Ndim x K] row-major (both K-contiguous).
// EPI 0: write fp32 C.  EPI 1: write hi/lo fp16 split of C.
template <int NT, int EPI>
__global__ void __launch_bounds__(256, 1)
gemm_kernel(const __half* __restrict__ pAh, const __half* __restrict__ pAl,
            const __half* __restrict__ pBh, const __half* __restrict__ pBl,
            float* __restrict__ pCf, __half* __restrict__ pChi, __half* __restrict__ pClo,
            int Kdim, int lda, int ldb, int ldc,
            long long sA, long long sB, long long sC) {
    extern __shared__ __align__(16) __half sm[];
    // stage layout: [Ah][Bh][Bl][Al?]  (halves)
    constexpr uint32_t oBh = TILE_A * 2;
    constexpr uint32_t oBl = oBh + TILE_B * 2;
    constexpr uint32_t oAl = oBl + TILE_B * 2;
    constexpr uint32_t STAGE_B =
        (NT == 3) ? (TILE_A * 2 * 2 + TILE_B * 2 * 2) : (TILE_A * 2 + TILE_B * 2 * 2);

    const int tid = threadIdx.x;
    const int bz = blockIdx.z;
    const int m0 = blockIdx.y * BM;
    const int n0 = blockIdx.x * BN;

    const __half* gAh = pAh + (size_t)bz * sA + (size_t)m0 * lda;
    const __half* gAl = (NT == 3) ? (pAl + (size_t)bz * sA + (size_t)m0 * lda) : gAh;
    const __half* gBh = pBh + (size_t)bz * sB + (size_t)n0 * ldb;
    const __half* gBl = pBl + (size_t)bz * sB + (size_t)n0 * ldb;

    // loader mapping: 256 threads; A rows lr, lr+64; B rows lr, +64, +128, +192
    const int lr = tid >> 2;
    const int lc = (tid & 3) * 8;

    const uint32_t smbase = (uint32_t)__cvta_generic_to_shared(sm);

    const int lane = tid & 31;
    const int wid = tid >> 5;
    const int wm0 = (wid & 1) * 64;     // 2 warps over M
    const int wn0 = (wid >> 1) * 64;    // 4 warps over N

    const uint32_t aoff =
        (uint32_t)(((wm0 + (lane & 15)) * LDS + ((lane >> 4) & 1) * 8) * 2);
    const uint32_t boff =
        (uint32_t)(((wn0 + (lane & 7) + ((lane >> 4) & 1) * 8) * LDS + ((lane >> 3) & 1) * 8) * 2);

    float acc[4][8][4];
#pragma unroll
    for (int i = 0; i < 4; i++)
#pragma unroll
        for (int j = 0; j < 8; j++)
#pragma unroll
            for (int k = 0; k < 4; k++) acc[i][j][k] = 0.f;

    // ---- stage load (cp.async) ----
    auto issue = [&](int st, int kt) {
        const uint32_t b = smbase + (uint32_t)st * STAGE_B;
        const uint32_t ra = (uint32_t)((lr * LDS + lc) * 2);
        const uint32_t rb = (uint32_t)((64 * LDS) * 2);
        cp16(b + ra, gAh + (size_t)lr * lda + kt + lc);
        cp16(b + ra + rb, gAh + (size_t)(lr + 64) * lda + kt + lc);
#pragma unroll
        for (int q = 0; q < 4; q++) {
            cp16(b + oBh + ra + q * rb, gBh + (size_t)(lr + 64 * q) * ldb + kt + lc);
            cp16(b + oBl + ra + q * rb, gBl + (size_t)(lr + 64 * q) * ldb + kt + lc);
        }
        if constexpr (NT == 3) {
            cp16(b + oAl + ra, gAl + (size_t)lr * lda + kt + lc);
            cp16(b + oAl + ra + rb, gAl + (size_t)(lr + 64) * lda + kt + lc);
        }
    };

    // ---- stage compute: 64x64 warp tile, term-major ----
    auto compute = [&](int st) {
        const uint32_t b = smbase + (uint32_t)st * STAGE_B;
        const uint32_t uA = b + aoff;
        const uint32_t uAl2 = b + oAl + aoff;
        const uint32_t uBh2 = b + oBh + boff;
        const uint32_t uBl2 = b + oBl + boff;
#pragma unroll
        for (int kk = 0; kk < 2; kk++) {
            uint32_t fAh[4][4], fAl[4][4], fBh[8][2], fBl[8][2];
#pragma unroll
            for (int mt = 0; mt < 4; mt++) {
                ldsm4(fAh[mt][0], fAh[mt][1], fAh[mt][2], fAh[mt][3],
                      uA + mt * (16 * LDS * 2) + kk * 32);
                if constexpr (NT == 3)
                    ldsm4(fAl[mt][0], fAl[mt][1], fAl[mt][2], fAl[mt][3],
                          uAl2 + mt * (16 * LDS * 2) + kk * 32);
            }
#pragma unroll
            for (int p = 0; p < 4; p++) {
                uint32_t r0, r1, r2, r3;
                ldsm4(r0, r1, r2, r3, uBh2 + p * (16 * LDS * 2) + kk * 32);
                fBh[2 * p][0] = r0; fBh[2 * p][1] = r1;
                fBh[2 * p + 1][0] = r2; fBh[2 * p + 1][1] = r3;
                ldsm4(r0, r1, r2, r3, uBl2 + p * (16 * LDS * 2) + kk * 32);
                fBl[2 * p][0] = r0; fBl[2 * p][1] = r1;
                fBl[2 * p + 1][0] = r2; fBl[2 * p + 1][1] = r3;
            }
            // term 1: Ah * Bh
#pragma unroll
            for (int mt = 0; mt < 4; mt++)
#pragma unroll
                for (int nt = 0; nt < 8; nt++)
                    mma16816(acc[mt][nt], fAh[mt], fBh[nt][0], fBh[nt][1]);
            // term 2: Ah * Bl
#pragma unroll
            for (int mt = 0; mt < 4; mt++)
#pragma unroll
                for (int nt = 0; nt < 8; nt++)
                    mma16816(acc[mt][nt], fAh[mt], fBl[nt][0], fBl[nt][1]);
            // term 3: Al * Bh
            if constexpr (NT == 3) {
#pragma unroll
                for (int mt = 0; mt < 4; mt++)
#pragma unroll
                    for (int nt = 0; nt < 8; nt++)
                        mma16816(acc[mt][nt], fAl[mt], fBh[nt][0], fBh[nt][1]);
            }
        }
    };

    // ---- 3-stage pipeline ----
    const int KT = Kdim / BK;
    issue(0, 0);
    cp_commit();
    issue(1, BK);
    cp_commit();
    int cur = 0;
    for (int it = 0; it < KT; it++) {
        cp_wait<1>();
        __syncthreads();
        if (it + 2 < KT) {
            int nx = cur + 2;
            if (nx >= NSTAGE) nx -= NSTAGE;
            issue(nx, (it + 2) * BK);
        }
        cp_commit();
        compute(cur);
        cur++;
        if (cur == NSTAGE) cur = 0;
    }

    // ---------------- epilogue ----------------
    const int g = lane >> 2, tq = lane & 3;
#pragma unroll
    for (int mt = 0; mt < 4; mt++) {
#pragma unroll
        for (int nt = 0; nt < 8; nt++) {
            const int r = m0 + wm0 + mt * 16 + g;
            const int c = n0 + wn0 + nt * 8 + tq * 2;
            if (EPI == 0) {
                float* C = pCf + (size_t)bz * sC;
                *(float2*)&C[(size_t)r * ldc + c] =
                    make_float2(acc[mt][nt][0], acc[mt][nt][1]);
                *(float2*)&C[(size_t)(r + 8) * ldc + c] =
                    make_float2(acc[mt][nt][2], acc[mt][nt][3]);
            } else {
                __half* Chi = pChi + (size_t)bz * sC;
                __half* Clo = pClo + (size_t)bz * sC;
                float v0 = acc[mt][nt][0], v1 = acc[mt][nt][1];
                float v2 = acc[mt][nt][2], v3 = acc[mt][nt][3];
                __half h0 = __float2half_rn(v0), h1 = __float2half_rn(v1);
                __half h2 = __float2half_rn(v2), h3 = __float2half_rn(v3);
                *(__half2*)&Chi[(size_t)r * ldc + c] = __halves2half2(h0, h1);
                *(__half2*)&Chi[(size_t)(r + 8) * ldc + c] = __halves2half2(h2, h3);
                *(__half2*)&Clo[(size_t)r * ldc + c] =
                    __halves2half2(__float2half_rn(v0 - __half2float(h0)),
                                   __float2half_rn(v1 - __half2float(h1)));
                *(__half2*)&Clo[(size_t)(r + 8) * ldc + c] =
                    __halves2half2(__float2half_rn(v2 - __half2float(h2)),
                                   __float2half_rn(v3 - __half2float(h3)));
            }
        }
    }
}

// ---------------- masked softmax: P = softmax(where(mask,E,-1e10)/32) ----------------
__global__ void softmax_kernel(const float* __restrict__ E, const int* __restrict__ mask,
                               __half* __restrict__ P) {
    const size_t base = (size_t)blockIdx.x * Ms;
    const int tid = threadIdx.x;
    __shared__ float redm[8];
    __shared__ float reds[8];

    const float4* E4 = (const float4*)(E + base);
    const int4* M4 = (const int4*)(mask + base);

    float v[8];
    float mx = -3.4e38f;
#pragma unroll
    for (int i = 0; i < 2; i++) {
        float4 e = E4[tid * 2 + i];
        int4 mk = M4[tid * 2 + i];
        float* vv = v + i * 4;
        vv[0] = mk.x ? e.x * 0.03125f : -3.125e8f;
        vv[1] = mk.y ? e.y * 0.03125f : -3.125e8f;
        vv[2] = mk.z ? e.z * 0.03125f : -3.125e8f;
        vv[3] = mk.w ? e.w * 0.03125f : -3.125e8f;
        mx = fmaxf(mx, fmaxf(fmaxf(vv[0], vv[1]), fmaxf(vv[2], vv[3])));
    }
#pragma unroll
    for (int o = 16; o; o >>= 1) mx = fmaxf(mx, __shfl_xor_sync(0xffffffffu, mx, o));
    if ((tid & 31) == 0) redm[tid >> 5] = mx;
    __syncthreads();
    if (tid < 8) {
        float m2 = redm[tid];
#pragma unroll
        for (int o = 4; o; o >>= 1) m2 = fmaxf(m2, __shfl_xor_sync(0xffu, m2, o));
        redm[tid] = m2;
    }
    __syncthreads();
    mx = redm[0];

    float s = 0.f;
#pragma unroll
    for (int i = 0; i < 8; i++) {
        v[i] = __expf(v[i] - mx);
        s += v[i];
    }
#pragma unroll
    for (int o = 16; o; o >>= 1) s += __shfl_xor_sync(0xffffffffu, s, o);
    if ((tid & 31) == 0) reds[tid >> 5] = s;
    __syncthreads();
    if (tid < 8) {
        float s2 = reds[tid];
#pragma unroll
        for (int o = 4; o; o >>= 1) s2 += __shfl_xor_sync(0xffu, s2, o);
        reds[tid] = s2;
    }
    __syncthreads();
    const float inv = 1.0f / reds[0];
    __half2* P2 = (__half2*)(P + base);
#pragma unroll
    for (int i = 0; i < 4; i++) {
        P2[tid * 4 + i] = __halves2half2(__float2half_rn(v[2 * i] * inv),
                                         __float2half_rn(v[2 * i + 1] * inv));
    }
}

// ---------------- launch ----------------
extern "C" void kernel_launch(void* const* d_in, const int* in_sizes, int n_in,
                              void* d_out, int out_size) {
    (void)in_sizes; (void)n_in; (void)out_size;
    const float* h1 = (const float*)d_in[0];
    const float* h2 = (const float*)d_in[1];
    const int* mask = (const int*)d_in[2];
    const float* Wq = (const float*)d_in[3];
    const float* Wk = (const float*)d_in[4];
    const float* Wv = (const float*)d_in[5];
    float* out = (float*)d_out;

    __half *h1h, *h1l, *h2h, *h2l, *Wqh, *Wql, *Wkh, *Wkl, *Wvh, *Wvl;
    __half *Qh, *Ql, *Kh, *Kl, *Vth, *Vtl, *P;
    float* E;
    cudaGetSymbolAddress((void**)&h1h, g_h1h);
    cudaGetSymbolAddress((void**)&h1l, g_h1l);
    cudaGetSymbolAddress((void**)&h2h, g_h2h);
    cudaGetSymbolAddress((void**)&h2l, g_h2l);
    cudaGetSymbolAddress((void**)&Wqh, g_Wqh);
    cudaGetSymbolAddress((void**)&Wql, g_Wql);
    cudaGetSymbolAddress((void**)&Wkh, g_Wkh);
    cudaGetSymbolAddress((void**)&Wkl, g_Wkl);
    cudaGetSymbolAddress((void**)&Wvh, g_Wvh);
    cudaGetSymbolAddress((void**)&Wvl, g_Wvl);
    cudaGetSymbolAddress((void**)&Qh, g_Qh);
    cudaGetSymbolAddress((void**)&Ql, g_Ql);
    cudaGetSymbolAddress((void**)&Kh, g_Kh);
    cudaGetSymbolAddress((void**)&Kl, g_Kl);
    cudaGetSymbolAddress((void**)&Vth, g_Vth);
    cudaGetSymbolAddress((void**)&Vtl, g_Vtl);
    cudaGetSymbolAddress((void**)&E, g_E);
    cudaGetSymbolAddress((void**)&P, g_P);

    const int smem3 = (TILE_A * 2 * 2 + TILE_B * 2 * 2) * NSTAGE;  // 184320 B
    const int smem2 = (TILE_A * 2 + TILE_B * 2 * 2) * NSTAGE;      // 153600 B
    cudaFuncSetAttribute(gemm_kernel<3, 1>, cudaFuncAttributeMaxDynamicSharedMemorySize, smem3);
    cudaFuncSetAttribute(gemm_kernel<3, 0>, cudaFuncAttributeMaxDynamicSharedMemorySize, smem3);
    cudaFuncSetAttribute(gemm_kernel<2, 0>, cudaFuncAttributeMaxDynamicSharedMemorySize, smem2);

    // fused hi/lo split, single launch
    split_all_kernel<<<(R4v + 255) / 256, 256>>>(
        (const float4*)h1, (const float4*)h2, (const float4*)Wq, (const float4*)Wk,
        (const float4*)Wv,
        (__half2*)h1h, (__half2*)h1l, (__half2*)h2h, (__half2*)h2l,
        (__half2*)Wqh, (__half2*)Wql, (__half2*)Wkh, (__half2*)Wkl,
        (__half2*)Wvh, (__half2*)Wvl);

    // Q = h1 * Wq^T (16384 x 1024 x 1024) -> split epilogue
    gemm_kernel<3, 1><<<dim3(Hh / BN, (Bz * Ns) / BM, 1), 256, smem3>>>(
        h1h, h1l, Wqh, Wql, nullptr, Qh, Ql, Dd, Dd, Dd, Hh, 0, 0, 0);
    // K = h2 * Wk^T
    gemm_kernel<3, 1><<<dim3(Hh / BN, (Bz * Ms) / BM, 1), 256, smem3>>>(
        h2h, h2l, Wkh, Wkl, nullptr, Kh, Kl, Dd, Dd, Dd, Hh, 0, 0, 0);
    // Vt[b][o][m] = Wv * h2[b]^T
    gemm_kernel<3, 1><<<dim3(Ms / BN, Oo / BM, Bz), 256, smem3>>>(
        Wvh, Wvl, h2h, h2l, nullptr, Vth, Vtl, Dd, Dd, Dd, Ms,
        0, (long long)Ms * Dd, (long long)Oo * Ms);
    // E[b] = Q[b] * K[b]^T (2048 x 2048 x 1024)
    gemm_kernel<3, 0><<<dim3(Ms / BN, Ns / BM, Bz), 256, smem3>>>(
        Qh, Ql, Kh, Kl, E, nullptr, nullptr, Hh, Hh, Hh, Ms,
        (long long)Ns * Hh, (long long)Ms * Hh, (long long)Ns * Ms);
    // masked softmax -> P (fp16)
    softmax_kernel<<<Bz * Ns, 256>>>(E, mask, P);
    // out[b] = P[b] * Vt[b]^T (2048 x 1024 x 2048), 2-term
    gemm_kernel<2, 0><<<dim3(Oo / BN, Ns / BM, Bz), 256, smem2>>>(
        P, nullptr, Vth, Vtl, out, nullptr, nullptr, Ms, Ms, Ms, Oo,
        (long long)Ns * Ms, (long long)Oo * Ms, (long long)Ns * Oo);
}

// round 8
// speedup vs baseline: 1.1512x; 1.1512x over previous
#include <cuda_runtime.h>
#include <cuda_fp16.h>
#include <cstdint>

#define Bz 8
#define Ns 2048
#define Ms 2048
#define Dd 1024
#define Hh 1024
#define Oo 1024

#define BM 128
#define BN 128
#define BK 32
#define LDS 40        // padded row stride in halves (80B, conflict-free ldmatrix)
#define NSTAGE 2

// ---------------- device scratch ----------------
__device__ __half g_h1h[Bz * Ns * Dd];
__device__ __half g_h1l[Bz * Ns * Dd];
__device__ __half g_h2h[Bz * Ms * Dd];
__device__ __half g_h2l[Bz * Ms * Dd];
__device__ __half g_Wqh[Hh * Dd];
__device__ __half g_Wql[Hh * Dd];
__device__ __half g_Wkh[Hh * Dd];
__device__ __half g_Wkl[Hh * Dd];
__device__ __half g_Wvh[Oo * Dd];
__device__ __half g_Wvl[Oo * Dd];
__device__ __half g_Qh[Bz * Ns * Hh];
__device__ __half g_Ql[Bz * Ns * Hh];
__device__ __half g_Kh[Bz * Ms * Hh];
__device__ __half g_Kl[Bz * Ms * Hh];
__device__ __half g_Vth[Bz * Oo * Ms];   // V transposed: [b][o][m]
__device__ __half g_Vtl[Bz * Oo * Ms];
__device__ float  g_E[(size_t)Bz * Ns * Ms];
__device__ __half g_P[(size_t)Bz * Ns * Ms];

// ---------------- fused fp32 -> fp16 hi/lo split ----------------
#define R0 4194304
#define R1 8388608
#define R2q 8650752
#define R3k 8912896
#define R4v 9175040

__global__ void split_all_kernel(const float4* __restrict__ h1, const float4* __restrict__ h2,
                                 const float4* __restrict__ Wq, const float4* __restrict__ Wk,
                                 const float4* __restrict__ Wv,
                                 __half2* __restrict__ h1h, __half2* __restrict__ h1l,
                                 __half2* __restrict__ h2h, __half2* __restrict__ h2l,
                                 __half2* __restrict__ Wqh, __half2* __restrict__ Wql,
                                 __half2* __restrict__ Wkh, __half2* __restrict__ Wkl,
                                 __half2* __restrict__ Wvh, __half2* __restrict__ Wvl) {
    int i = blockIdx.x * blockDim.x + threadIdx.x;
    const float4* src;
    __half2 *hi, *lo;
    int j;
    if (i < R0)       { src = h1; hi = h1h; lo = h1l; j = i; }
    else if (i < R1)  { src = h2; hi = h2h; lo = h2l; j = i - R0; }
    else if (i < R2q) { src = Wq; hi = Wqh; lo = Wql; j = i - R1; }
    else if (i < R3k) { src = Wk; hi = Wkh; lo = Wkl; j = i - R2q; }
    else if (i < R4v) { src = Wv; hi = Wvh; lo = Wvl; j = i - R3k; }
    else return;
    float4 v = src[j];
    __half a = __float2half_rn(v.x), b = __float2half_rn(v.y);
    __half c = __float2half_rn(v.z), d = __float2half_rn(v.w);
    hi[2 * j + 0] = __halves2half2(a, b);
    hi[2 * j + 1] = __halves2half2(c, d);
    lo[2 * j + 0] = __halves2half2(__float2half_rn(v.x - __half2float(a)),
                                   __float2half_rn(v.y - __half2float(b)));
    lo[2 * j + 1] = __halves2half2(__float2half_rn(v.z - __half2float(c)),
                                   __float2half_rn(v.w - __half2float(d)));
}

// ---------------- PTX helpers ----------------
__device__ __forceinline__ void ldsm4(uint32_t& r0, uint32_t& r1, uint32_t& r2, uint32_t& r3,
                                      uint32_t addr) {
    asm volatile("ldmatrix.sync.aligned.m8n8.x4.shared.b16 {%0,%1,%2,%3}, [%4];"
                 : "=r"(r0), "=r"(r1), "=r"(r2), "=r"(r3)
                 : "r"(addr));
}

__device__ __forceinline__ void mma16816(float* c, const uint32_t* a, uint32_t b0, uint32_t b1) {
    asm volatile("mma.sync.aligned.m16n8k16.row.col.f32.f16.f16.f32 "
                 "{%0,%1,%2,%3}, {%4,%5,%6,%7}, {%8,%9}, {%0,%1,%2,%3};"
                 : "+f"(c[0]), "+f"(c[1]), "+f"(c[2]), "+f"(c[3])
                 : "r"(a[0]), "r"(a[1]), "r"(a[2]), "r"(a[3]), "r"(b0), "r"(b1));
}

__device__ __forceinline__ void cp16(uint32_t dst, const void* src) {
    asm volatile("cp.async.cg.shared.global [%0], [%1], 16;" :: "r"(dst), "l"(src));
}
__device__ __forceinline__ void cp_commit() { asm volatile("cp.async.commit_group;"); }
template <int N>
__device__ __forceinline__ void cp_wait() { asm volatile("cp.async.wait_group %0;" :: "n"(N)); }

// ---------------- double-buffered split GEMM, 2 CTAs/SM ----------------
// C = Ah*Bh^T + Ah*Bl^T (+ Al*Bh^T if NT==3)
// A: [Mdim x K] row-major, B: [Ndim x K] row-major (both K-contiguous).
// EPI 0: write fp32 C.  EPI 1: write hi/lo fp16 split of C.
template <int NT, int EPI>
__global__ void __launch_bounds__(256, 2)
gemm_kernel(const __half* __restrict__ pAh, const __half* __restrict__ pAl,
            const __half* __restrict__ pBh, const __half* __restrict__ pBl,
            float* __restrict__ pCf, __half* __restrict__ pChi, __half* __restrict__ pClo,
            int Kdim, int lda, int ldb, int ldc,
            long long sA, long long sB, long long sC) {
    extern __shared__ __align__(16) __half sm[];
    constexpr int TILE = BM * LDS;                 // halves per tile
    constexpr int NTILE = (NT == 3) ? 4 : 3;       // Ah, Bh, Bl, [Al]
    constexpr uint32_t STAGE_B = NTILE * TILE * 2; // bytes per stage

    const int tid = threadIdx.x;
    const int bz = blockIdx.z;
    const int m0 = blockIdx.y * BM;
    const int n0 = blockIdx.x * BN;

    const __half* gAh = pAh + (size_t)bz * sA + (size_t)m0 * lda;
    const __half* gAl = (NT == 3) ? (pAl + (size_t)bz * sA + (size_t)m0 * lda) : gAh;
    const __half* gBh = pBh + (size_t)bz * sB + (size_t)n0 * ldb;
    const __half* gBl = pBl + (size_t)bz * sB + (size_t)n0 * ldb;

    // loader mapping: 256 threads -> rows lr and lr+64, 16B column chunk lc
    const int lr = tid >> 2;
    const int lc = (tid & 3) * 8;

    const uint32_t smbase = (uint32_t)__cvta_generic_to_shared(sm);

    const int lane = tid & 31;
    const int wid = tid >> 5;
    const int wm0 = (wid & 1) * 64;
    const int wn0 = (wid >> 1) * 32;

    const uint32_t aoff =
        (uint32_t)(((wm0 + (lane & 15)) * LDS + ((lane >> 4) & 1) * 8) * 2);
    const uint32_t boff =
        (uint32_t)(((wn0 + (lane & 7) + ((lane >> 4) & 1) * 8) * LDS + ((lane >> 3) & 1) * 8) * 2);

    float acc[4][4][4];
#pragma unroll
    for (int i = 0; i < 4; i++)
#pragma unroll
        for (int j = 0; j < 4; j++)
#pragma unroll
            for (int k = 0; k < 4; k++) acc[i][j][k] = 0.f;

    // ---- stage load (cp.async) ----
    auto issue = [&](int st, int kt) {
        const uint32_t b = smbase + (uint32_t)st * STAGE_B;
        const uint32_t d0 = b + (uint32_t)((lr * LDS + lc) * 2);
        const uint32_t d1 = b + (uint32_t)(((lr + 64) * LDS + lc) * 2);
        cp16(d0, gAh + (size_t)lr * lda + kt + lc);
        cp16(d1, gAh + (size_t)(lr + 64) * lda + kt + lc);
        cp16(d0 + TILE * 2, gBh + (size_t)lr * ldb + kt + lc);
        cp16(d1 + TILE * 2, gBh + (size_t)(lr + 64) * ldb + kt + lc);
        cp16(d0 + 2 * TILE * 2, gBl + (size_t)lr * ldb + kt + lc);
        cp16(d1 + 2 * TILE * 2, gBl + (size_t)(lr + 64) * ldb + kt + lc);
        if constexpr (NT == 3) {
            cp16(d0 + 3 * TILE * 2, gAl + (size_t)lr * lda + kt + lc);
            cp16(d1 + 3 * TILE * 2, gAl + (size_t)(lr + 64) * lda + kt + lc);
        }
        cp_commit();
    };

    // ---- stage compute: Bh-consumers first, then overwrite B frags with Bl ----
    // live-register diet: acc64 + fAh16 + fAl16 + fB8 -> fits 128-reg budget
    auto compute = [&](int st) {
        const uint32_t b = smbase + (uint32_t)st * STAGE_B;
        const uint32_t uA = b + aoff;
        const uint32_t uB = b + TILE * 2 + boff;
        const uint32_t uBl2 = b + 2 * TILE * 2 + boff;
        const uint32_t uAl2 = b + 3 * TILE * 2 + aoff;
#pragma unroll
        for (int kk = 0; kk < 2; kk++) {
            uint32_t fAh[4][4], fB[4][2];
#pragma unroll
            for (int mt = 0; mt < 4; mt++)
                ldsm4(fAh[mt][0], fAh[mt][1], fAh[mt][2], fAh[mt][3],
                      uA + mt * (16 * LDS * 2) + kk * 32);
#pragma unroll
            for (int p = 0; p < 2; p++) {
                uint32_t r0, r1, r2, r3;
                ldsm4(r0, r1, r2, r3, uB + p * (16 * LDS * 2) + kk * 32);
                fB[2 * p][0] = r0; fB[2 * p][1] = r1;
                fB[2 * p + 1][0] = r2; fB[2 * p + 1][1] = r3;
            }
            // term 1: Ah * Bh
#pragma unroll
            for (int mt = 0; mt < 4; mt++)
#pragma unroll
                for (int nt = 0; nt < 4; nt++)
                    mma16816(acc[mt][nt], fAh[mt], fB[nt][0], fB[nt][1]);
            // term 3: Al * Bh (Al frags live only here)
            if constexpr (NT == 3) {
                uint32_t fAl[4][4];
#pragma unroll
                for (int mt = 0; mt < 4; mt++)
                    ldsm4(fAl[mt][0], fAl[mt][1], fAl[mt][2], fAl[mt][3],
                          uAl2 + mt * (16 * LDS * 2) + kk * 32);
#pragma unroll
                for (int mt = 0; mt < 4; mt++)
#pragma unroll
                    for (int nt = 0; nt < 4; nt++)
                        mma16816(acc[mt][nt], fAl[mt], fB[nt][0], fB[nt][1]);
            }
            // overwrite B frags with Bl, term 2: Ah * Bl
#pragma unroll
            for (int p = 0; p < 2; p++) {
                uint32_t r0, r1, r2, r3;
                ldsm4(r0, r1, r2, r3, uBl2 + p * (16 * LDS * 2) + kk * 32);
                fB[2 * p][0] = r0; fB[2 * p][1] = r1;
                fB[2 * p + 1][0] = r2; fB[2 * p + 1][1] = r3;
            }
#pragma unroll
            for (int mt = 0; mt < 4; mt++)
#pragma unroll
                for (int nt = 0; nt < 4; nt++)
                    mma16816(acc[mt][nt], fAh[mt], fB[nt][0], fB[nt][1]);
        }
    };

    // ---- double-buffer pipeline: wait -> sync -> issue(t+1) -> compute(t) ----
    const int KT = Kdim / BK;
    issue(0, 0);
    int cur = 0;
    for (int t = 0; t < KT; t++) {
        cp_wait<0>();
        __syncthreads();
        if (t + 1 < KT) issue(1 - cur, (t + 1) * BK);
        compute(cur);
        cur ^= 1;
    }

    // ---------------- epilogue ----------------
    const int g = lane >> 2, tq = lane & 3;
#pragma unroll
    for (int mt = 0; mt < 4; mt++) {
#pragma unroll
        for (int nt = 0; nt < 4; nt++) {
            const int r = m0 + wm0 + mt * 16 + g;
            const int c = n0 + wn0 + nt * 8 + tq * 2;
            if (EPI == 0) {
                float* C = pCf + (size_t)bz * sC;
                *(float2*)&C[(size_t)r * ldc + c] =
                    make_float2(acc[mt][nt][0], acc[mt][nt][1]);
                *(float2*)&C[(size_t)(r + 8) * ldc + c] =
                    make_float2(acc[mt][nt][2], acc[mt][nt][3]);
            } else {
                __half* Chi = pChi + (size_t)bz * sC;
                __half* Clo = pClo + (size_t)bz * sC;
                float v0 = acc[mt][nt][0], v1 = acc[mt][nt][1];
                float v2 = acc[mt][nt][2], v3 = acc[mt][nt][3];
                __half h0 = __float2half_rn(v0), h1 = __float2half_rn(v1);
                __half h2 = __float2half_rn(v2), h3 = __float2half_rn(v3);
                *(__half2*)&Chi[(size_t)r * ldc + c] = __halves2half2(h0, h1);
                *(__half2*)&Chi[(size_t)(r + 8) * ldc + c] = __halves2half2(h2, h3);
                *(__half2*)&Clo[(size_t)r * ldc + c] =
                    __halves2half2(__float2half_rn(v0 - __half2float(h0)),
                                   __float2half_rn(v1 - __half2float(h1)));
                *(__half2*)&Clo[(size_t)(r + 8) * ldc + c] =
                    __halves2half2(__float2half_rn(v2 - __half2float(h2)),
                                   __float2half_rn(v3 - __half2float(h3)));
            }
        }
    }
}

// ---------------- masked softmax: P = softmax(where(mask,E,-1e10)/32) ----------------
__global__ void softmax_kernel(const float* __restrict__ E, const int* __restrict__ mask,
                               __half* __restrict__ P) {
    const size_t base = (size_t)blockIdx.x * Ms;
    const int tid = threadIdx.x;
    __shared__ float redm[8];
    __shared__ float reds[8];

    const float4* E4 = (const float4*)(E + base);
    const int4* M4 = (const int4*)(mask + base);

    float v[8];
    float mx = -3.4e38f;
#pragma unroll
    for (int i = 0; i < 2; i++) {
        float4 e = E4[tid * 2 + i];
        int4 mk = M4[tid * 2 + i];
        float* vv = v + i * 4;
        vv[0] = mk.x ? e.x * 0.03125f : -3.125e8f;
        vv[1] = mk.y ? e.y * 0.03125f : -3.125e8f;
        vv[2] = mk.z ? e.z * 0.03125f : -3.125e8f;
        vv[3] = mk.w ? e.w * 0.03125f : -3.125e8f;
        mx = fmaxf(mx, fmaxf(fmaxf(vv[0], vv[1]), fmaxf(vv[2], vv[3])));
    }
#pragma unroll
    for (int o = 16; o; o >>= 1) mx = fmaxf(mx, __shfl_xor_sync(0xffffffffu, mx, o));
    if ((tid & 31) == 0) redm[tid >> 5] = mx;
    __syncthreads();
    if (tid < 8) {
        float m2 = redm[tid];
#pragma unroll
        for (int o = 4; o; o >>= 1) m2 = fmaxf(m2, __shfl_xor_sync(0xffu, m2, o));
        redm[tid] = m2;
    }
    __syncthreads();
    mx = redm[0];

    float s = 0.f;
#pragma unroll
    for (int i = 0; i < 8; i++) {
        v[i] = __expf(v[i] - mx);
        s += v[i];
    }
#pragma unroll
    for (int o = 16; o; o >>= 1) s += __shfl_xor_sync(0xffffffffu, s, o);
    if ((tid & 31) == 0) reds[tid >> 5] = s;
    __syncthreads();
    if (tid < 8) {
        float s2 = reds[tid];
#pragma unroll
        for (int o = 4; o; o >>= 1) s2 += __shfl_xor_sync(0xffu, s2, o);
        reds[tid] = s2;
    }
    __syncthreads();
    const float inv = 1.0f / reds[0];
    __half2* P2 = (__half2*)(P + base);
#pragma unroll
    for (int i = 0; i < 4; i++) {
        P2[tid * 4 + i] = __halves2half2(__float2half_rn(v[2 * i] * inv),
                                         __float2half_rn(v[2 * i + 1] * inv));
    }
}

// ---------------- launch ----------------
extern "C" void kernel_launch(void* const* d_in, const int* in_sizes, int n_in,
                              void* d_out, int out_size) {
    (void)in_sizes; (void)n_in; (void)out_size;
    const float* h1 = (const float*)d_in[0];
    const float* h2 = (const float*)d_in[1];
    const int* mask = (const int*)d_in[2];
    const float* Wq = (const float*)d_in[3];
    const float* Wk = (const float*)d_in[4];
    const float* Wv = (const float*)d_in[5];
    float* out = (float*)d_out;

    __half *h1h, *h1l, *h2h, *h2l, *Wqh, *Wql, *Wkh, *Wkl, *Wvh, *Wvl;
    __half *Qh, *Ql, *Kh, *Kl, *Vth, *Vtl, *P;
    float* E;
    cudaGetSymbolAddress((void**)&h1h, g_h1h);
    cudaGetSymbolAddress((void**)&h1l, g_h1l);
    cudaGetSymbolAddress((void**)&h2h, g_h2h);
    cudaGetSymbolAddress((void**)&h2l, g_h2l);
    cudaGetSymbolAddress((void**)&Wqh, g_Wqh);
    cudaGetSymbolAddress((void**)&Wql, g_Wql);
    cudaGetSymbolAddress((void**)&Wkh, g_Wkh);
    cudaGetSymbolAddress((void**)&Wkl, g_Wkl);
    cudaGetSymbolAddress((void**)&Wvh, g_Wvh);
    cudaGetSymbolAddress((void**)&Wvl, g_Wvl);
    cudaGetSymbolAddress((void**)&Qh, g_Qh);
    cudaGetSymbolAddress((void**)&Ql, g_Ql);
    cudaGetSymbolAddress((void**)&Kh, g_Kh);
    cudaGetSymbolAddress((void**)&Kl, g_Kl);
    cudaGetSymbolAddress((void**)&Vth, g_Vth);
    cudaGetSymbolAddress((void**)&Vtl, g_Vtl);
    cudaGetSymbolAddress((void**)&E, g_E);
    cudaGetSymbolAddress((void**)&P, g_P);

    const int smem3 = 4 * BM * LDS * 2 * NSTAGE;   // 81920 B  -> 2 CTAs/SM
    const int smem2 = 3 * BM * LDS * 2 * NSTAGE;   // 61440 B  -> 2 CTAs/SM
    cudaFuncSetAttribute(gemm_kernel<3, 1>, cudaFuncAttributeMaxDynamicSharedMemorySize, smem3);
    cudaFuncSetAttribute(gemm_kernel<3, 0>, cudaFuncAttributeMaxDynamicSharedMemorySize, smem3);
    cudaFuncSetAttribute(gemm_kernel<2, 0>, cudaFuncAttributeMaxDynamicSharedMemorySize, smem2);

    // fused hi/lo split, single launch
    split_all_kernel<<<(R4v + 255) / 256, 256>>>(
        (const float4*)h1, (const float4*)h2, (const float4*)Wq, (const float4*)Wk,
        (const float4*)Wv,
        (__half2*)h1h, (__half2*)h1l, (__half2*)h2h, (__half2*)h2l,
        (__half2*)Wqh, (__half2*)Wql, (__half2*)Wkh, (__half2*)Wkl,
        (__half2*)Wvh, (__half2*)Wvl);

    // Q = h1 * Wq^T (16384 x 1024 x 1024) -> split epilogue
    gemm_kernel<3, 1><<<dim3(Hh / BN, (Bz * Ns) / BM, 1), 256, smem3>>>(
        h1h, h1l, Wqh, Wql, nullptr, Qh, Ql, Dd, Dd, Dd, Hh, 0, 0, 0);
    // K = h2 * Wk^T
    gemm_kernel<3, 1><<<dim3(Hh / BN, (Bz * Ms) / BM, 1), 256, smem3>>>(
        h2h, h2l, Wkh, Wkl, nullptr, Kh, Kl, Dd, Dd, Dd, Hh, 0, 0, 0);
    // Vt[b][o][m] = Wv * h2[b]^T
    gemm_kernel<3, 1><<<dim3(Ms / BN, Oo / BM, Bz), 256, smem3>>>(
        Wvh, Wvl, h2h, h2l, nullptr, Vth, Vtl, Dd, Dd, Dd, Ms,
        0, (long long)Ms * Dd, (long long)Oo * Ms);
    // E[b] = Q[b] * K[b]^T (2048 x 2048 x 1024)
    gemm_kernel<3, 0><<<dim3(Ms / BN, Ns / BM, Bz), 256, smem3>>>(
        Qh, Ql, Kh, Kl, E, nullptr, nullptr, Hh, Hh, Hh, Ms,
        (long long)Ns * Hh, (long long)Ms * Hh, (long long)Ns * Ms);
    // masked softmax -> P (fp16)
    softmax_kernel<<<Bz * Ns, 256>>>(E, mask, P);
    // out[b] = P[b] * Vt[b]^T (2048 x 1024 x 2048), 2-term
    gemm_kernel<2, 0><<<dim3(Oo / BN, Ns / BM, Bz), 256, smem2>>>(
        P, nullptr, Vth, Vtl, out, nullptr, nullptr, Ms, Ms, Ms, Oo,
        (long long)Ns * Ms, (long long)Oo * Ms, (long long)Ns * Oo);
}

// round 9
// speedup vs baseline: 1.5223x; 1.3223x over previous
#include <cuda_runtime.h>
#include <cuda_fp16.h>
#include <cstdint>

#define Bz 8
#define Ns 2048
#define Ms 2048
#define Dd 1024
#define Hh 1024
#define Oo 1024

#define BM 128
#define BN 128
#define BK 32
#define LDS 40        // padded row stride in halves (80B, conflict-free ldmatrix)
#define NSTAGE 2

// ---------------- device scratch ----------------
__device__ __half g_h1h[Bz * Ns * Dd];
__device__ __half g_h2h[Bz * Ms * Dd];
__device__ __half g_h2l[Bz * Ms * Dd];
__device__ __half g_Wqh[Hh * Dd];
__device__ __half g_Wql[Hh * Dd];
__device__ __half g_Wkh[Hh * Dd];
__device__ __half g_Wkl[Hh * Dd];
__device__ __half g_Wvh[Oo * Dd];
__device__ __half g_Qh[Bz * Ns * Hh];
__device__ __half g_Kh[Bz * Ms * Hh];
__device__ __half g_Kl[Bz * Ms * Hh];
__device__ __half g_Vth[Bz * Oo * Ms];   // V transposed: [b][o][m]
__device__ __half g_Vtl[Bz * Oo * Ms];
__device__ float  g_E[(size_t)Bz * Ns * Ms];
__device__ __half g_P[(size_t)Bz * Ns * Ms];

// ---------------- fused fp32 -> fp16 split ----------------
// h1 -> hi only; h2 -> hi+lo; Wq,Wk -> hi+lo; Wv -> hi only
#define R0 4194304    // h1 float4 count
#define R1 8388608    // + h2
#define R2q 8650752   // + Wq
#define R3k 8912896   // + Wk
#define R4v 9175040   // + Wv

__global__ void split_all_kernel(const float4* __restrict__ h1, const float4* __restrict__ h2,
                                 const float4* __restrict__ Wq, const float4* __restrict__ Wk,
                                 const float4* __restrict__ Wv,
                                 __half2* __restrict__ h1h,
                                 __half2* __restrict__ h2h, __half2* __restrict__ h2l,
                                 __half2* __restrict__ Wqh, __half2* __restrict__ Wql,
                                 __half2* __restrict__ Wkh, __half2* __restrict__ Wkl,
                                 __half2* __restrict__ Wvh) {
    int i = blockIdx.x * blockDim.x + threadIdx.x;
    const float4* src;
    __half2 *hi, *lo = nullptr;
    int j;
    if (i < R0)       { src = h1; hi = h1h; j = i; }
    else if (i < R1)  { src = h2; hi = h2h; lo = h2l; j = i - R0; }
    else if (i < R2q) { src = Wq; hi = Wqh; lo = Wql; j = i - R1; }
    else if (i < R3k) { src = Wk; hi = Wkh; lo = Wkl; j = i - R2q; }
    else if (i < R4v) { src = Wv; hi = Wvh; j = i - R3k; }
    else return;
    float4 v = src[j];
    __half a = __float2half_rn(v.x), b = __float2half_rn(v.y);
    __half c = __float2half_rn(v.z), d = __float2half_rn(v.w);
    hi[2 * j + 0] = __halves2half2(a, b);
    hi[2 * j + 1] = __halves2half2(c, d);
    if (lo) {
        lo[2 * j + 0] = __halves2half2(__float2half_rn(v.x - __half2float(a)),
                                       __float2half_rn(v.y - __half2float(b)));
        lo[2 * j + 1] = __halves2half2(__float2half_rn(v.z - __half2float(c)),
                                       __float2half_rn(v.w - __half2float(d)));
    }
}

// ---------------- PTX helpers ----------------
__device__ __forceinline__ void ldsm4(uint32_t& r0, uint32_t& r1, uint32_t& r2, uint32_t& r3,
                                      uint32_t addr) {
    asm volatile("ldmatrix.sync.aligned.m8n8.x4.shared.b16 {%0,%1,%2,%3}, [%4];"
                 : "=r"(r0), "=r"(r1), "=r"(r2), "=r"(r3)
                 : "r"(addr));
}

__device__ __forceinline__ void mma16816(float* c, const uint32_t* a, uint32_t b0, uint32_t b1) {
    asm volatile("mma.sync.aligned.m16n8k16.row.col.f32.f16.f16.f32 "
                 "{%0,%1,%2,%3}, {%4,%5,%6,%7}, {%8,%9}, {%0,%1,%2,%3};"
                 : "+f"(c[0]), "+f"(c[1]), "+f"(c[2]), "+f"(c[3])
                 : "r"(a[0]), "r"(a[1]), "r"(a[2]), "r"(a[3]), "r"(b0), "r"(b1));
}

__device__ __forceinline__ void cp16(uint32_t dst, const void* src) {
    asm volatile("cp.async.cg.shared.global [%0], [%1], 16;" :: "r"(dst), "l"(src));
}
__device__ __forceinline__ void cp_commit() { asm volatile("cp.async.commit_group;"); }
template <int N>
__device__ __forceinline__ void cp_wait() { asm volatile("cp.async.wait_group %0;" :: "n"(N)); }

// ---------------- double-buffered 2-term split GEMM, 2 CTAs/SM ----------------
// C = Ah*Bh^T + Ah*Bl^T
// A: [Mdim x K] row-major, B: [Ndim x K] row-major (both K-contiguous).
// EPI 0: fp32 C.  EPI 1: hi/lo fp16 split of C.  EPI 2: fp16 hi only.
template <int EPI>
__global__ void __launch_bounds__(256, 2)
gemm_kernel(const __half* __restrict__ pAh,
            const __half* __restrict__ pBh, const __half* __restrict__ pBl,
            float* __restrict__ pCf, __half* __restrict__ pChi, __half* __restrict__ pClo,
            int Kdim, int lda, int ldb, int ldc,
            long long sA, long long sB, long long sC) {
    extern __shared__ __align__(16) __half sm[];
    constexpr int TILE = BM * LDS;                 // halves per tile
    constexpr uint32_t STAGE_B = 3 * TILE * 2;     // Ah, Bh, Bl

    const int tid = threadIdx.x;
    const int bz = blockIdx.z;
    const int m0 = blockIdx.y * BM;
    const int n0 = blockIdx.x * BN;

    const __half* gAh = pAh + (size_t)bz * sA + (size_t)m0 * lda;
    const __half* gBh = pBh + (size_t)bz * sB + (size_t)n0 * ldb;
    const __half* gBl = pBl + (size_t)bz * sB + (size_t)n0 * ldb;

    // loader mapping: 256 threads -> rows lr and lr+64, 16B column chunk lc
    const int lr = tid >> 2;
    const int lc = (tid & 3) * 8;

    const uint32_t smbase = (uint32_t)__cvta_generic_to_shared(sm);

    const int lane = tid & 31;
    const int wid = tid >> 5;
    const int wm0 = (wid & 1) * 64;
    const int wn0 = (wid >> 1) * 32;

    const uint32_t aoff =
        (uint32_t)(((wm0 + (lane & 15)) * LDS + ((lane >> 4) & 1) * 8) * 2);
    const uint32_t boff =
        (uint32_t)(((wn0 + (lane & 7) + ((lane >> 4) & 1) * 8) * LDS + ((lane >> 3) & 1) * 8) * 2);

    float acc[4][4][4];
#pragma unroll
    for (int i = 0; i < 4; i++)
#pragma unroll
        for (int j = 0; j < 4; j++)
#pragma unroll
            for (int k = 0; k < 4; k++) acc[i][j][k] = 0.f;

    // ---- stage load (cp.async): 6 chunks per thread ----
    auto issue = [&](int st, int kt) {
        const uint32_t b = smbase + (uint32_t)st * STAGE_B;
        const uint32_t d0 = b + (uint32_t)((lr * LDS + lc) * 2);
        const uint32_t d1 = b + (uint32_t)(((lr + 64) * LDS + lc) * 2);
        cp16(d0, gAh + (size_t)lr * lda + kt + lc);
        cp16(d1, gAh + (size_t)(lr + 64) * lda + kt + lc);
        cp16(d0 + TILE * 2, gBh + (size_t)lr * ldb + kt + lc);
        cp16(d1 + TILE * 2, gBh + (size_t)(lr + 64) * ldb + kt + lc);
        cp16(d0 + 2 * TILE * 2, gBl + (size_t)lr * ldb + kt + lc);
        cp16(d1 + 2 * TILE * 2, gBl + (size_t)(lr + 64) * ldb + kt + lc);
        cp_commit();
    };

    // ---- stage compute: Ah*Bh then Ah*Bl (B frags overwritten) ----
    auto compute = [&](int st) {
        const uint32_t b = smbase + (uint32_t)st * STAGE_B;
        const uint32_t uA = b + aoff;
        const uint32_t uBh = b + TILE * 2 + boff;
        const uint32_t uBl = b + 2 * TILE * 2 + boff;
#pragma unroll
        for (int kk = 0; kk < 2; kk++) {
            uint32_t fAh[4][4], fB[4][2];
#pragma unroll
            for (int mt = 0; mt < 4; mt++)
                ldsm4(fAh[mt][0], fAh[mt][1], fAh[mt][2], fAh[mt][3],
                      uA + mt * (16 * LDS * 2) + kk * 32);
#pragma unroll
            for (int p = 0; p < 2; p++) {
                uint32_t r0, r1, r2, r3;
                ldsm4(r0, r1, r2, r3, uBh + p * (16 * LDS * 2) + kk * 32);
                fB[2 * p][0] = r0; fB[2 * p][1] = r1;
                fB[2 * p + 1][0] = r2; fB[2 * p + 1][1] = r3;
            }
#pragma unroll
            for (int mt = 0; mt < 4; mt++)
#pragma unroll
                for (int nt = 0; nt < 4; nt++)
                    mma16816(acc[mt][nt], fAh[mt], fB[nt][0], fB[nt][1]);
#pragma unroll
            for (int p = 0; p < 2; p++) {
                uint32_t r0, r1, r2, r3;
                ldsm4(r0, r1, r2, r3, uBl + p * (16 * LDS * 2) + kk * 32);
                fB[2 * p][0] = r0; fB[2 * p][1] = r1;
                fB[2 * p + 1][0] = r2; fB[2 * p + 1][1] = r3;
            }
#pragma unroll
            for (int mt = 0; mt < 4; mt++)
#pragma unroll
                for (int nt = 0; nt < 4; nt++)
                    mma16816(acc[mt][nt], fAh[mt], fB[nt][0], fB[nt][1]);
        }
    };

    // ---- double-buffer pipeline ----
    const int KT = Kdim / BK;
    issue(0, 0);
    int cur = 0;
    for (int t = 0; t < KT; t++) {
        cp_wait<0>();
        __syncthreads();
        if (t + 1 < KT) issue(1 - cur, (t + 1) * BK);
        compute(cur);
        cur ^= 1;
    }

    // ---------------- epilogue ----------------
    const int g = lane >> 2, tq = lane & 3;
#pragma unroll
    for (int mt = 0; mt < 4; mt++) {
#pragma unroll
        for (int nt = 0; nt < 4; nt++) {
            const int r = m0 + wm0 + mt * 16 + g;
            const int c = n0 + wn0 + nt * 8 + tq * 2;
            float v0 = acc[mt][nt][0], v1 = acc[mt][nt][1];
            float v2 = acc[mt][nt][2], v3 = acc[mt][nt][3];
            if (EPI == 0) {
                float* C = pCf + (size_t)bz * sC;
                *(float2*)&C[(size_t)r * ldc + c] = make_float2(v0, v1);
                *(float2*)&C[(size_t)(r + 8) * ldc + c] = make_float2(v2, v3);
            } else {
                __half* Chi = pChi + (size_t)bz * sC;
                __half h0 = __float2half_rn(v0), h1 = __float2half_rn(v1);
                __half h2 = __float2half_rn(v2), h3 = __float2half_rn(v3);
                *(__half2*)&Chi[(size_t)r * ldc + c] = __halves2half2(h0, h1);
                *(__half2*)&Chi[(size_t)(r + 8) * ldc + c] = __halves2half2(h2, h3);
                if (EPI == 1) {
                    __half* Clo = pClo + (size_t)bz * sC;
                    *(__half2*)&Clo[(size_t)r * ldc + c] =
                        __halves2half2(__float2half_rn(v0 - __half2float(h0)),
                                       __float2half_rn(v1 - __half2float(h1)));
                    *(__half2*)&Clo[(size_t)(r + 8) * ldc + c] =
                        __halves2half2(__float2half_rn(v2 - __half2float(h2)),
                                       __float2half_rn(v3 - __half2float(h3)));
                }
            }
        }
    }
}

// ---------------- masked softmax: P = softmax(where(mask,E,-1e10)/32) ----------------
__global__ void softmax_kernel(const float* __restrict__ E, const int* __restrict__ mask,
                               __half* __restrict__ P) {
    const size_t base = (size_t)blockIdx.x * Ms;
    const int tid = threadIdx.x;
    __shared__ float redm[8];
    __shared__ float reds[8];

    const float4* E4 = (const float4*)(E + base);
    const int4* M4 = (const int4*)(mask + base);

    float v[8];
    float mx = -3.4e38f;
#pragma unroll
    for (int i = 0; i < 2; i++) {
        float4 e = E4[tid * 2 + i];
        int4 mk = M4[tid * 2 + i];
        float* vv = v + i * 4;
        vv[0] = mk.x ? e.x * 0.03125f : -3.125e8f;
        vv[1] = mk.y ? e.y * 0.03125f : -3.125e8f;
        vv[2] = mk.z ? e.z * 0.03125f : -3.125e8f;
        vv[3] = mk.w ? e.w * 0.03125f : -3.125e8f;
        mx = fmaxf(mx, fmaxf(fmaxf(vv[0], vv[1]), fmaxf(vv[2], vv[3])));
    }
#pragma unroll
    for (int o = 16; o; o >>= 1) mx = fmaxf(mx, __shfl_xor_sync(0xffffffffu, mx, o));
    if ((tid & 31) == 0) redm[tid >> 5] = mx;
    __syncthreads();
    if (tid < 8) {
        float m2 = redm[tid];
#pragma unroll
        for (int o = 4; o; o >>= 1) m2 = fmaxf(m2, __shfl_xor_sync(0xffu, m2, o));
        redm[tid] = m2;
    }
    __syncthreads();
    mx = redm[0];

    float s = 0.f;
#pragma unroll
    for (int i = 0; i < 8; i++) {
        v[i] = __expf(v[i] - mx);
        s += v[i];
    }
#pragma unroll
    for (int o = 16; o; o >>= 1) s += __shfl_xor_sync(0xffffffffu, s, o);
    if ((tid & 31) == 0) reds[tid >> 5] = s;
    __syncthreads();
    if (tid < 8) {
        float s2 = reds[tid];
#pragma unroll
        for (int o = 4; o; o >>= 1) s2 += __shfl_xor_sync(0xffu, s2, o);
        reds[tid] = s2;
    }
    __syncthreads();
    const float inv = 1.0f / reds[0];
    __half2* P2 = (__half2*)(P + base);
#pragma unroll
    for (int i = 0; i < 4; i++) {
        P2[tid * 4 + i] = __halves2half2(__float2half_rn(v[2 * i] * inv),
                                         __float2half_rn(v[2 * i + 1] * inv));
    }
}

// ---------------- launch ----------------
extern "C" void kernel_launch(void* const* d_in, const int* in_sizes, int n_in,
                              void* d_out, int out_size) {
    (void)in_sizes; (void)n_in; (void)out_size;
    const float* h1 = (const float*)d_in[0];
    const float* h2 = (const float*)d_in[1];
    const int* mask = (const int*)d_in[2];
    const float* Wq = (const float*)d_in[3];
    const float* Wk = (const float*)d_in[4];
    const float* Wv = (const float*)d_in[5];
    float* out = (float*)d_out;

    __half *h1h, *h2h, *h2l, *Wqh, *Wql, *Wkh, *Wkl, *Wvh;
    __half *Qh, *Kh, *Kl, *Vth, *Vtl, *P;
    float* E;
    cudaGetSymbolAddress((void**)&h1h, g_h1h);
    cudaGetSymbolAddress((void**)&h2h, g_h2h);
    cudaGetSymbolAddress((void**)&h2l, g_h2l);
    cudaGetSymbolAddress((void**)&Wqh, g_Wqh);
    cudaGetSymbolAddress((void**)&Wql, g_Wql);
    cudaGetSymbolAddress((void**)&Wkh, g_Wkh);
    cudaGetSymbolAddress((void**)&Wkl, g_Wkl);
    cudaGetSymbolAddress((void**)&Wvh, g_Wvh);
    cudaGetSymbolAddress((void**)&Qh, g_Qh);
    cudaGetSymbolAddress((void**)&Kh, g_Kh);
    cudaGetSymbolAddress((void**)&Kl, g_Kl);
    cudaGetSymbolAddress((void**)&Vth, g_Vth);
    cudaGetSymbolAddress((void**)&Vtl, g_Vtl);
    cudaGetSymbolAddress((void**)&E, g_E);
    cudaGetSymbolAddress((void**)&P, g_P);

    const int smem2 = 3 * BM * LDS * 2 * NSTAGE;   // 61440 B -> 2 CTAs/SM
    cudaFuncSetAttribute(gemm_kernel<0>, cudaFuncAttributeMaxDynamicSharedMemorySize, smem2);
    cudaFuncSetAttribute(gemm_kernel<1>, cudaFuncAttributeMaxDynamicSharedMemorySize, smem2);
    cudaFuncSetAttribute(gemm_kernel<2>, cudaFuncAttributeMaxDynamicSharedMemorySize, smem2);

    // fused split, single launch
    split_all_kernel<<<(R4v + 255) / 256, 256>>>(
        (const float4*)h1, (const float4*)h2, (const float4*)Wq, (const float4*)Wk,
        (const float4*)Wv,
        (__half2*)h1h, (__half2*)h2h, (__half2*)h2l,
        (__half2*)Wqh, (__half2*)Wql, (__half2*)Wkh, (__half2*)Wkl,
        (__half2*)Wvh);

    // Qh = h1h * (Wqh+Wql)^T  (16384 x 1024 x 1024), fp16-hi epilogue
    gemm_kernel<2><<<dim3(Hh / BN, (Bz * Ns) / BM, 1), 256, smem2>>>(
        h1h, Wqh, Wql, nullptr, Qh, nullptr, Dd, Dd, Dd, Hh, 0, 0, 0);
    // K = h2h * (Wkh+Wkl)^T -> hi/lo split
    gemm_kernel<1><<<dim3(Hh / BN, (Bz * Ms) / BM, 1), 256, smem2>>>(
        h2h, Wkh, Wkl, nullptr, Kh, Kl, Dd, Dd, Dd, Hh, 0, 0, 0);
    // Vt[b] = Wvh * (h2h+h2l)[b]^T -> hi/lo split
    gemm_kernel<1><<<dim3(Ms / BN, Oo / BM, Bz), 256, smem2>>>(
        Wvh, h2h, h2l, nullptr, Vth, Vtl, Dd, Dd, Dd, Ms,
        0, (long long)Ms * Dd, (long long)Oo * Ms);
    // E[b] = Qh[b] * (Kh+Kl)[b]^T (2048 x 2048 x 1024), fp32
    gemm_kernel<0><<<dim3(Ms / BN, Ns / BM, Bz), 256, smem2>>>(
        Qh, Kh, Kl, E, nullptr, nullptr, Hh, Hh, Hh, Ms,
        (long long)Ns * Hh, (long long)Ms * Hh, (long long)Ns * Ms);
    // masked softmax -> P (fp16)
    softmax_kernel<<<Bz * Ns, 256>>>(E, mask, P);
    // out[b] = P[b] * (Vth+Vtl)[b]^T (2048 x 1024 x 2048), fp32
    gemm_kernel<0><<<dim3(Oo / BN, Ns / BM, Bz), 256, smem2>>>(
        P, Vth, Vtl, out, nullptr, nullptr, Ms, Ms, Ms, Oo,
        (long long)Ns * Ms, (long long)Oo * Ms, (long long)Ns * Oo);
}

// round 10
// speedup vs baseline: 1.6197x; 1.0640x over previous
#include <cuda_runtime.h>
#include <cuda_fp16.h>
#include <cstdint>

#define Bz 8
#define Ns 2048
#define Ms 2048
#define Dd 1024
#define Hh 1024
#define Oo 1024

#define BM 128
#define BN 128
#define BK 64
#define LDS 72        // padded row stride in halves (144B; conflict-free ldmatrix)
#define NSTAGE 2

// ---------------- device scratch ----------------
__device__ __half g_h1h[Bz * Ns * Dd];
__device__ __half g_h2h[Bz * Ms * Dd];
__device__ __half g_h2l[Bz * Ms * Dd];
__device__ __half g_Wqh[Hh * Dd];
__device__ __half g_Wql[Hh * Dd];
__device__ __half g_Wkh[Hh * Dd];
__device__ __half g_Wkl[Hh * Dd];
__device__ __half g_Wvh[Oo * Dd];
__device__ __half g_Qh[Bz * Ns * Hh];
__device__ __half g_Kh[Bz * Ms * Hh];
__device__ __half g_Kl[Bz * Ms * Hh];
__device__ __half g_Vth[Bz * Oo * Ms];   // V transposed: [b][o][m]
__device__ __half g_Vtl[Bz * Oo * Ms];
__device__ float  g_E[(size_t)Bz * Ns * Ms];
__device__ __half g_P[(size_t)Bz * Ns * Ms];

// ---------------- fused fp32 -> fp16 split ----------------
// h1 -> hi only; h2 -> hi+lo; Wq,Wk -> hi+lo; Wv -> hi only
#define R0 4194304    // h1 float4 count
#define R1 8388608    // + h2
#define R2q 8650752   // + Wq
#define R3k 8912896   // + Wk
#define R4v 9175040   // + Wv

__global__ void split_all_kernel(const float4* __restrict__ h1, const float4* __restrict__ h2,
                                 const float4* __restrict__ Wq, const float4* __restrict__ Wk,
                                 const float4* __restrict__ Wv,
                                 __half2* __restrict__ h1h,
                                 __half2* __restrict__ h2h, __half2* __restrict__ h2l,
                                 __half2* __restrict__ Wqh, __half2* __restrict__ Wql,
                                 __half2* __restrict__ Wkh, __half2* __restrict__ Wkl,
                                 __half2* __restrict__ Wvh) {
    int i = blockIdx.x * blockDim.x + threadIdx.x;
    const float4* src;
    __half2 *hi, *lo = nullptr;
    int j;
    if (i < R0)       { src = h1; hi = h1h; j = i; }
    else if (i < R1)  { src = h2; hi = h2h; lo = h2l; j = i - R0; }
    else if (i < R2q) { src = Wq; hi = Wqh; lo = Wql; j = i - R1; }
    else if (i < R3k) { src = Wk; hi = Wkh; lo = Wkl; j = i - R2q; }
    else if (i < R4v) { src = Wv; hi = Wvh; j = i - R3k; }
    else return;
    float4 v = src[j];
    __half a = __float2half_rn(v.x), b = __float2half_rn(v.y);
    __half c = __float2half_rn(v.z), d = __float2half_rn(v.w);
    hi[2 * j + 0] = __halves2half2(a, b);
    hi[2 * j + 1] = __halves2half2(c, d);
    if (lo) {
        lo[2 * j + 0] = __halves2half2(__float2half_rn(v.x - __half2float(a)),
                                       __float2half_rn(v.y - __half2float(b)));
        lo[2 * j + 1] = __halves2half2(__float2half_rn(v.z - __half2float(c)),
                                       __float2half_rn(v.w - __half2float(d)));
    }
}

// ---------------- PTX helpers ----------------
__device__ __forceinline__ void ldsm4(uint32_t& r0, uint32_t& r1, uint32_t& r2, uint32_t& r3,
                                      uint32_t addr) {
    asm volatile("ldmatrix.sync.aligned.m8n8.x4.shared.b16 {%0,%1,%2,%3}, [%4];"
                 : "=r"(r0), "=r"(r1), "=r"(r2), "=r"(r3)
                 : "r"(addr));
}

__device__ __forceinline__ void mma16816(float* c, const uint32_t* a, uint32_t b0, uint32_t b1) {
    asm volatile("mma.sync.aligned.m16n8k16.row.col.f32.f16.f16.f32 "
                 "{%0,%1,%2,%3}, {%4,%5,%6,%7}, {%8,%9}, {%0,%1,%2,%3};"
                 : "+f"(c[0]), "+f"(c[1]), "+f"(c[2]), "+f"(c[3])
                 : "r"(a[0]), "r"(a[1]), "r"(a[2]), "r"(a[3]), "r"(b0), "r"(b1));
}

__device__ __forceinline__ void cp16(uint32_t dst, const void* src) {
    asm volatile("cp.async.cg.shared.global [%0], [%1], 16;" :: "r"(dst), "l"(src));
}
__device__ __forceinline__ void cp_commit() { asm volatile("cp.async.commit_group;"); }
template <int N>
__device__ __forceinline__ void cp_wait() { asm volatile("cp.async.wait_group %0;" :: "n"(N)); }

// ---------------- double-buffered 2-term split GEMM, BK=64, 2 CTAs/SM ----------------
// C = Ah*Bh^T + Ah*Bl^T
// A: [Mdim x K] row-major, B: [Ndim x K] row-major (both K-contiguous).
// EPI 0: fp32 C.  EPI 1: hi/lo fp16 split of C.  EPI 2: fp16 hi only.
template <int EPI>
__global__ void __launch_bounds__(256, 2)
gemm_kernel(const __half* __restrict__ pAh,
            const __half* __restrict__ pBh, const __half* __restrict__ pBl,
            float* __restrict__ pCf, __half* __restrict__ pChi, __half* __restrict__ pClo,
            int Kdim, int lda, int ldb, int ldc,
            long long sA, long long sB, long long sC) {
    extern __shared__ __align__(16) __half sm[];
    constexpr int TILE = BM * LDS;                 // halves per tile (9216)
    constexpr uint32_t STAGE_B = 3 * TILE * 2;     // Ah, Bh, Bl = 55296 B

    const int tid = threadIdx.x;
    const int bz = blockIdx.z;
    const int m0 = blockIdx.y * BM;
    const int n0 = blockIdx.x * BN;

    const __half* gAh = pAh + (size_t)bz * sA + (size_t)m0 * lda;
    const __half* gBh = pBh + (size_t)bz * sB + (size_t)n0 * ldb;
    const __half* gBl = pBl + (size_t)bz * sB + (size_t)n0 * ldb;

    const uint32_t smbase = (uint32_t)__cvta_generic_to_shared(sm);

    const int lane = tid & 31;
    const int wid = tid >> 5;
    const int wm0 = (wid & 1) * 64;
    const int wn0 = (wid >> 1) * 32;

    const uint32_t aoff =
        (uint32_t)(((wm0 + (lane & 15)) * LDS + ((lane >> 4) & 1) * 8) * 2);
    const uint32_t boff =
        (uint32_t)(((wn0 + (lane & 7) + ((lane >> 4) & 1) * 8) * LDS + ((lane >> 3) & 1) * 8) * 2);

    float acc[4][4][4];
#pragma unroll
    for (int i = 0; i < 4; i++)
#pragma unroll
        for (int j = 0; j < 4; j++)
#pragma unroll
            for (int k = 0; k < 4; k++) acc[i][j][k] = 0.f;

    // ---- stage load (cp.async): 1024 16B chunks per tile, 4 per thread per tile ----
    auto issue = [&](int st, int kt) {
        const uint32_t b = smbase + (uint32_t)st * STAGE_B;
#pragma unroll
        for (int i = 0; i < 4; i++) {
            const int q = i * 256 + tid;
            const int r = q >> 3, c = (q & 7) * 8;   // row 0..127, col chunk (halves)
            const uint32_t d = b + (uint32_t)((r * LDS + c) * 2);
            cp16(d, gAh + (size_t)r * lda + kt + c);
            cp16(d + TILE * 2, gBh + (size_t)r * ldb + kt + c);
            cp16(d + 2 * TILE * 2, gBl + (size_t)r * ldb + kt + c);
        }
        cp_commit();
    };

    // ---- stage compute: 4 kk steps of K=16; Ah*Bh then Ah*Bl per kk ----
    auto compute = [&](int st) {
        const uint32_t b = smbase + (uint32_t)st * STAGE_B;
        const uint32_t uA = b + aoff;
        const uint32_t uBh = b + TILE * 2 + boff;
        const uint32_t uBl = b + 2 * TILE * 2 + boff;
#pragma unroll
        for (int kk = 0; kk < 4; kk++) {
            uint32_t fAh[4][4], fB[4][2];
#pragma unroll
            for (int mt = 0; mt < 4; mt++)
                ldsm4(fAh[mt][0], fAh[mt][1], fAh[mt][2], fAh[mt][3],
                      uA + mt * (16 * LDS * 2) + kk * 32);
#pragma unroll
            for (int p = 0; p < 2; p++) {
                uint32_t r0, r1, r2, r3;
                ldsm4(r0, r1, r2, r3, uBh + p * (16 * LDS * 2) + kk * 32);
                fB[2 * p][0] = r0; fB[2 * p][1] = r1;
                fB[2 * p + 1][0] = r2; fB[2 * p + 1][1] = r3;
            }
#pragma unroll
            for (int mt = 0; mt < 4; mt++)
#pragma unroll
                for (int nt = 0; nt < 4; nt++)
                    mma16816(acc[mt][nt], fAh[mt], fB[nt][0], fB[nt][1]);
#pragma unroll
            for (int p = 0; p < 2; p++) {
                uint32_t r0, r1, r2, r3;
                ldsm4(r0, r1, r2, r3, uBl + p * (16 * LDS * 2) + kk * 32);
                fB[2 * p][0] = r0; fB[2 * p][1] = r1;
                fB[2 * p + 1][0] = r2; fB[2 * p + 1][1] = r3;
            }
#pragma unroll
            for (int mt = 0; mt < 4; mt++)
#pragma unroll
                for (int nt = 0; nt < 4; nt++)
                    mma16816(acc[mt][nt], fAh[mt], fB[nt][0], fB[nt][1]);
        }
    };

    // ---- double-buffer pipeline (KT = Kdim/64) ----
    const int KT = Kdim / BK;
    issue(0, 0);
    int cur = 0;
    for (int t = 0; t < KT; t++) {
        cp_wait<0>();
        __syncthreads();
        if (t + 1 < KT) issue(1 - cur, (t + 1) * BK);
        compute(cur);
        cur ^= 1;
    }

    // ---------------- epilogue ----------------
    const int g = lane >> 2, tq = lane & 3;
#pragma unroll
    for (int mt = 0; mt < 4; mt++) {
#pragma unroll
        for (int nt = 0; nt < 4; nt++) {
            const int r = m0 + wm0 + mt * 16 + g;
            const int c = n0 + wn0 + nt * 8 + tq * 2;
            float v0 = acc[mt][nt][0], v1 = acc[mt][nt][1];
            float v2 = acc[mt][nt][2], v3 = acc[mt][nt][3];
            if (EPI == 0) {
                float* C = pCf + (size_t)bz * sC;
                *(float2*)&C[(size_t)r * ldc + c] = make_float2(v0, v1);
                *(float2*)&C[(size_t)(r + 8) * ldc + c] = make_float2(v2, v3);
            } else {
                __half* Chi = pChi + (size_t)bz * sC;
                __half h0 = __float2half_rn(v0), h1 = __float2half_rn(v1);
                __half h2 = __float2half_rn(v2), h3 = __float2half_rn(v3);
                *(__half2*)&Chi[(size_t)r * ldc + c] = __halves2half2(h0, h1);
                *(__half2*)&Chi[(size_t)(r + 8) * ldc + c] = __halves2half2(h2, h3);
                if (EPI == 1) {
                    __half* Clo = pClo + (size_t)bz * sC;
                    *(__half2*)&Clo[(size_t)r * ldc + c] =
                        __halves2half2(__float2half_rn(v0 - __half2float(h0)),
                                       __float2half_rn(v1 - __half2float(h1)));
                    *(__half2*)&Clo[(size_t)(r + 8) * ldc + c] =
                        __halves2half2(__float2half_rn(v2 - __half2float(h2)),
                                       __float2half_rn(v3 - __half2float(h3)));
                }
            }
        }
    }
}

// ---------------- masked softmax: P = softmax(where(mask,E,-1e10)/32) ----------------
__global__ void softmax_kernel(const float* __restrict__ E, const int* __restrict__ mask,
                               __half* __restrict__ P) {
    const size_t base = (size_t)blockIdx.x * Ms;
    const int tid = threadIdx.x;
    __shared__ float redm[8];
    __shared__ float reds[8];

    const float4* E4 = (const float4*)(E + base);
    const int4* M4 = (const int4*)(mask + base);

    float v[8];
    float mx = -3.4e38f;
#pragma unroll
    for (int i = 0; i < 2; i++) {
        float4 e = E4[tid * 2 + i];
        int4 mk = M4[tid * 2 + i];
        float* vv = v + i * 4;
        vv[0] = mk.x ? e.x * 0.03125f : -3.125e8f;
        vv[1] = mk.y ? e.y * 0.03125f : -3.125e8f;
        vv[2] = mk.z ? e.z * 0.03125f : -3.125e8f;
        vv[3] = mk.w ? e.w * 0.03125f : -3.125e8f;
        mx = fmaxf(mx, fmaxf(fmaxf(vv[0], vv[1]), fmaxf(vv[2], vv[3])));
    }
#pragma unroll
    for (int o = 16; o; o >>= 1) mx = fmaxf(mx, __shfl_xor_sync(0xffffffffu, mx, o));
    if ((tid & 31) == 0) redm[tid >> 5] = mx;
    __syncthreads();
    if (tid < 8) {
        float m2 = redm[tid];
#pragma unroll
        for (int o = 4; o; o >>= 1) m2 = fmaxf(m2, __shfl_xor_sync(0xffu, m2, o));
        redm[tid] = m2;
    }
    __syncthreads();
    mx = redm[0];

    float s = 0.f;
#pragma unroll
    for (int i = 0; i < 8; i++) {
        v[i] = __expf(v[i] - mx);
        s += v[i];
    }
#pragma unroll
    for (int o = 16; o; o >>= 1) s += __shfl_xor_sync(0xffffffffu, s, o);
    if ((tid & 31) == 0) reds[tid >> 5] = s;
    __syncthreads();
    if (tid < 8) {
        float s2 = reds[tid];
#pragma unroll
        for (int o = 4; o; o >>= 1) s2 += __shfl_xor_sync(0xffu, s2, o);
        reds[tid] = s2;
    }
    __syncthreads();
    const float inv = 1.0f / reds[0];
    __half2* P2 = (__half2*)(P + base);
#pragma unroll
    for (int i = 0; i < 4; i++) {
        P2[tid * 4 + i] = __halves2half2(__float2half_rn(v[2 * i] * inv),
                                         __float2half_rn(v[2 * i + 1] * inv));
    }
}

// ---------------- launch ----------------
extern "C" void kernel_launch(void* const* d_in, const int* in_sizes, int n_in,
                              void* d_out, int out_size) {
    (void)in_sizes; (void)n_in; (void)out_size;
    const float* h1 = (const float*)d_in[0];
    const float* h2 = (const float*)d_in[1];
    const int* mask = (const int*)d_in[2];
    const float* Wq = (const float*)d_in[3];
    const float* Wk = (const float*)d_in[4];
    const float* Wv = (const float*)d_in[5];
    float* out = (float*)d_out;

    __half *h1h, *h2h, *h2l, *Wqh, *Wql, *Wkh, *Wkl, *Wvh;
    __half *Qh, *Kh, *Kl, *Vth, *Vtl, *P;
    float* E;
    cudaGetSymbolAddress((void**)&h1h, g_h1h);
    cudaGetSymbolAddress((void**)&h2h, g_h2h);
    cudaGetSymbolAddress((void**)&h2l, g_h2l);
    cudaGetSymbolAddress((void**)&Wqh, g_Wqh);
    cudaGetSymbolAddress((void**)&Wql, g_Wql);
    cudaGetSymbolAddress((void**)&Wkh, g_Wkh);
    cudaGetSymbolAddress((void**)&Wkl, g_Wkl);
    cudaGetSymbolAddress((void**)&Wvh, g_Wvh);
    cudaGetSymbolAddress((void**)&Qh, g_Qh);
    cudaGetSymbolAddress((void**)&Kh, g_Kh);
    cudaGetSymbolAddress((void**)&Kl, g_Kl);
    cudaGetSymbolAddress((void**)&Vth, g_Vth);
    cudaGetSymbolAddress((void**)&Vtl, g_Vtl);
    cudaGetSymbolAddress((void**)&E, g_E);
    cudaGetSymbolAddress((void**)&P, g_P);

    const int smem2 = 3 * BM * LDS * 2 * NSTAGE;   // 110592 B -> still 2 CTAs/SM
    cudaFuncSetAttribute(gemm_kernel<0>, cudaFuncAttributeMaxDynamicSharedMemorySize, smem2);
    cudaFuncSetAttribute(gemm_kernel<1>, cudaFuncAttributeMaxDynamicSharedMemorySize, smem2);
    cudaFuncSetAttribute(gemm_kernel<2>, cudaFuncAttributeMaxDynamicSharedMemorySize, smem2);

    // fused split, single launch
    split_all_kernel<<<(R4v + 255) / 256, 256>>>(
        (const float4*)h1, (const float4*)h2, (const float4*)Wq, (const float4*)Wk,
        (const float4*)Wv,
        (__half2*)h1h, (__half2*)h2h, (__half2*)h2l,
        (__half2*)Wqh, (__half2*)Wql, (__half2*)Wkh, (__half2*)Wkl,
        (__half2*)Wvh);

    // Qh = h1h * (Wqh+Wql)^T  (16384 x 1024 x 1024), fp16-hi epilogue
    gemm_kernel<2><<<dim3(Hh / BN, (Bz * Ns) / BM, 1), 256, smem2>>>(
        h1h, Wqh, Wql, nullptr, Qh, nullptr, Dd, Dd, Dd, Hh, 0, 0, 0);
    // K = h2h * (Wkh+Wkl)^T -> hi/lo split
    gemm_kernel<1><<<dim3(Hh / BN, (Bz * Ms) / BM, 1), 256, smem2>>>(
        h2h, Wkh, Wkl, nullptr, Kh, Kl, Dd, Dd, Dd, Hh, 0, 0, 0);
    // Vt[b] = Wvh * (h2h+h2l)[b]^T -> hi/lo split
    gemm_kernel<1><<<dim3(Ms / BN, Oo / BM, Bz), 256, smem2>>>(
        Wvh, h2h, h2l, nullptr, Vth, Vtl, Dd, Dd, Dd, Ms,
        0, (long long)Ms * Dd, (long long)Oo * Ms);
    // E[b] = Qh[b] * (Kh+Kl)[b]^T (2048 x 2048 x 1024), fp32
    gemm_kernel<0><<<dim3(Ms / BN, Ns / BM, Bz), 256, smem2>>>(
        Qh, Kh, Kl, E, nullptr, nullptr, Hh, Hh, Hh, Ms,
        (long long)Ns * Hh, (long long)Ms * Hh, (long long)Ns * Ms);
    // masked softmax -> P (fp16)
    softmax_kernel<<<Bz * Ns, 256>>>(E, mask, P);
    // out[b] = P[b] * (Vth+Vtl)[b]^T (2048 x 1024 x 2048), fp32
    gemm_kernel<0><<<dim3(Oo / BN, Ns / BM, Bz), 256, smem2>>>(
        P, Vth, Vtl, out, nullptr, nullptr, Ms, Ms, Ms, Oo,
        (long long)Ns * Ms, (long long)Oo * Ms, (long long)Ns * Oo);
}

// round 11
// speedup vs baseline: 2.1161x; 1.3065x over previous
#include <cuda_runtime.h>
#include <cuda_fp16.h>
#include <cstdint>

#define Bz 8
#define Ns 2048
#define Ms 2048
#define Dd 1024
#define Hh 1024
#define Oo 1024

#define BM 128
#define BN 128
#define BK 64
#define LDS 72        // padded row stride in halves (144B; conflict-free ldmatrix)
#define NSTAGE 2

// ---------------- device scratch ----------------
__device__ __half g_h1h[Bz * Ns * Dd];
__device__ __half g_h2h[Bz * Ms * Dd];
__device__ __half g_h2l[Bz * Ms * Dd];
__device__ __half g_Wqh[Hh * Dd];
__device__ __half g_Wql[Hh * Dd];
__device__ __half g_Wkh[Hh * Dd];
__device__ __half g_Wkl[Hh * Dd];
__device__ __half g_Wvh[Oo * Dd];
__device__ __half g_Qh[Bz * Ns * Hh];
__device__ __half g_Kh[Bz * Ms * Hh];
__device__ __half g_Vth[Bz * Oo * Ms];   // V transposed: [b][o][m]
__device__ float  g_E[(size_t)Bz * Ns * Ms];
__device__ __half g_P[(size_t)Bz * Ns * Ms];

// ---------------- fused fp32 -> fp16 split ----------------
// h1 -> hi only; h2 -> hi+lo; Wq,Wk -> hi+lo; Wv -> hi only
#define R0 4194304    // h1 float4 count
#define R1 8388608    // + h2
#define R2q 8650752   // + Wq
#define R3k 8912896   // + Wk
#define R4v 9175040   // + Wv

__global__ void split_all_kernel(const float4* __restrict__ h1, const float4* __restrict__ h2,
                                 const float4* __restrict__ Wq, const float4* __restrict__ Wk,
                                 const float4* __restrict__ Wv,
                                 __half2* __restrict__ h1h,
                                 __half2* __restrict__ h2h, __half2* __restrict__ h2l,
                                 __half2* __restrict__ Wqh, __half2* __restrict__ Wql,
                                 __half2* __restrict__ Wkh, __half2* __restrict__ Wkl,
                                 __half2* __restrict__ Wvh) {
    int i = blockIdx.x * blockDim.x + threadIdx.x;
    const float4* src;
    __half2 *hi, *lo = nullptr;
    int j;
    if (i < R0)       { src = h1; hi = h1h; j = i; }
    else if (i < R1)  { src = h2; hi = h2h; lo = h2l; j = i - R0; }
    else if (i < R2q) { src = Wq; hi = Wqh; lo = Wql; j = i - R1; }
    else if (i < R3k) { src = Wk; hi = Wkh; lo = Wkl; j = i - R2q; }
    else if (i < R4v) { src = Wv; hi = Wvh; j = i - R3k; }
    else return;
    float4 v = src[j];
    __half a = __float2half_rn(v.x), b = __float2half_rn(v.y);
    __half c = __float2half_rn(v.z), d = __float2half_rn(v.w);
    hi[2 * j + 0] = __halves2half2(a, b);
    hi[2 * j + 1] = __halves2half2(c, d);
    if (lo) {
        lo[2 * j + 0] = __halves2half2(__float2half_rn(v.x - __half2float(a)),
                                       __float2half_rn(v.y - __half2float(b)));
        lo[2 * j + 1] = __halves2half2(__float2half_rn(v.z - __half2float(c)),
                                       __float2half_rn(v.w - __half2float(d)));
    }
}

// ---------------- PTX helpers ----------------
__device__ __forceinline__ void ldsm4(uint32_t& r0, uint32_t& r1, uint32_t& r2, uint32_t& r3,
                                      uint32_t addr) {
    asm volatile("ldmatrix.sync.aligned.m8n8.x4.shared.b16 {%0,%1,%2,%3}, [%4];"
                 : "=r"(r0), "=r"(r1), "=r"(r2), "=r"(r3)
                 : "r"(addr));
}

__device__ __forceinline__ void mma16816(float* c, const uint32_t* a, uint32_t b0, uint32_t b1) {
    asm volatile("mma.sync.aligned.m16n8k16.row.col.f32.f16.f16.f32 "
                 "{%0,%1,%2,%3}, {%4,%5,%6,%7}, {%8,%9}, {%0,%1,%2,%3};"
                 : "+f"(c[0]), "+f"(c[1]), "+f"(c[2]), "+f"(c[3])
                 : "r"(a[0]), "r"(a[1]), "r"(a[2]), "r"(a[3]), "r"(b0), "r"(b1));
}

__device__ __forceinline__ void cp16(uint32_t dst, const void* src) {
    asm volatile("cp.async.cg.shared.global [%0], [%1], 16;" :: "r"(dst), "l"(src));
}
__device__ __forceinline__ void cp_commit() { asm volatile("cp.async.commit_group;"); }
template <int N>
__device__ __forceinline__ void cp_wait() { asm volatile("cp.async.wait_group %0;" :: "n"(N)); }

// ---------------- double-buffered split GEMM, BK=64, 2 CTAs/SM ----------------
// NT=2: C = Ah*Bh^T + Ah*Bl^T.   NT=1: C = Ah*Bh^T.
// A: [Mdim x K] row-major, B: [Ndim x K] row-major (both K-contiguous).
// EPI 0: fp32 C.  EPI 1: hi/lo fp16 split of C.  EPI 2: fp16 hi only.
template <int EPI, int NT>
__global__ void __launch_bounds__(256, 2)
gemm_kernel(const __half* __restrict__ pAh,
            const __half* __restrict__ pBh, const __half* __restrict__ pBl,
            float* __restrict__ pCf, __half* __restrict__ pChi, __half* __restrict__ pClo,
            int Kdim, int lda, int ldb, int ldc,
            long long sA, long long sB, long long sC) {
    extern __shared__ __align__(16) __half sm[];
    constexpr int TILE = BM * LDS;                          // halves per tile (9216)
    constexpr uint32_t STAGE_B = (NT + 1) * TILE * 2;       // Ah, Bh[, Bl]

    const int tid = threadIdx.x;
    const int bz = blockIdx.z;
    const int m0 = blockIdx.y * BM;
    const int n0 = blockIdx.x * BN;

    const __half* gAh = pAh + (size_t)bz * sA + (size_t)m0 * lda;
    const __half* gBh = pBh + (size_t)bz * sB + (size_t)n0 * ldb;
    const __half* gBl = (NT == 2) ? (pBl + (size_t)bz * sB + (size_t)n0 * ldb) : gBh;

    const uint32_t smbase = (uint32_t)__cvta_generic_to_shared(sm);

    const int lane = tid & 31;
    const int wid = tid >> 5;
    const int wm0 = (wid & 1) * 64;
    const int wn0 = (wid >> 1) * 32;

    const uint32_t aoff =
        (uint32_t)(((wm0 + (lane & 15)) * LDS + ((lane >> 4) & 1) * 8) * 2);
    const uint32_t boff =
        (uint32_t)(((wn0 + (lane & 7) + ((lane >> 4) & 1) * 8) * LDS + ((lane >> 3) & 1) * 8) * 2);

    float acc[4][4][4];
#pragma unroll
    for (int i = 0; i < 4; i++)
#pragma unroll
        for (int j = 0; j < 4; j++)
#pragma unroll
            for (int k = 0; k < 4; k++) acc[i][j][k] = 0.f;

    // ---- stage load (cp.async): 4 chunks per thread per tile ----
    auto issue = [&](int st, int kt) {
        const uint32_t b = smbase + (uint32_t)st * STAGE_B;
#pragma unroll
        for (int i = 0; i < 4; i++) {
            const int q = i * 256 + tid;
            const int r = q >> 3, c = (q & 7) * 8;   // row 0..127, col chunk (halves)
            const uint32_t d = b + (uint32_t)((r * LDS + c) * 2);
            cp16(d, gAh + (size_t)r * lda + kt + c);
            cp16(d + TILE * 2, gBh + (size_t)r * ldb + kt + c);
            if constexpr (NT == 2)
                cp16(d + 2 * TILE * 2, gBl + (size_t)r * ldb + kt + c);
        }
        cp_commit();
    };

    // ---- stage compute: 4 kk steps of K=16 ----
    auto compute = [&](int st) {
        const uint32_t b = smbase + (uint32_t)st * STAGE_B;
        const uint32_t uA = b + aoff;
        const uint32_t uBh = b + TILE * 2 + boff;
        const uint32_t uBl = b + 2 * TILE * 2 + boff;
#pragma unroll
        for (int kk = 0; kk < 4; kk++) {
            uint32_t fAh[4][4], fB[4][2];
#pragma unroll
            for (int mt = 0; mt < 4; mt++)
                ldsm4(fAh[mt][0], fAh[mt][1], fAh[mt][2], fAh[mt][3],
                      uA + mt * (16 * LDS * 2) + kk * 32);
#pragma unroll
            for (int p = 0; p < 2; p++) {
                uint32_t r0, r1, r2, r3;
                ldsm4(r0, r1, r2, r3, uBh + p * (16 * LDS * 2) + kk * 32);
                fB[2 * p][0] = r0; fB[2 * p][1] = r1;
                fB[2 * p + 1][0] = r2; fB[2 * p + 1][1] = r3;
            }
#pragma unroll
            for (int mt = 0; mt < 4; mt++)
#pragma unroll
                for (int nt = 0; nt < 4; nt++)
                    mma16816(acc[mt][nt], fAh[mt], fB[nt][0], fB[nt][1]);
            if constexpr (NT == 2) {
#pragma unroll
                for (int p = 0; p < 2; p++) {
                    uint32_t r0, r1, r2, r3;
                    ldsm4(r0, r1, r2, r3, uBl + p * (16 * LDS * 2) + kk * 32);
                    fB[2 * p][0] = r0; fB[2 * p][1] = r1;
                    fB[2 * p + 1][0] = r2; fB[2 * p + 1][1] = r3;
                }
#pragma unroll
                for (int mt = 0; mt < 4; mt++)
#pragma unroll
                    for (int nt = 0; nt < 4; nt++)
                        mma16816(acc[mt][nt], fAh[mt], fB[nt][0], fB[nt][1]);
            }
        }
    };

    // ---- double-buffer pipeline (KT = Kdim/64) ----
    const int KT = Kdim / BK;
    issue(0, 0);
    int cur = 0;
    for (int t = 0; t < KT; t++) {
        cp_wait<0>();
        __syncthreads();
        if (t + 1 < KT) issue(1 - cur, (t + 1) * BK);
        compute(cur);
        cur ^= 1;
    }

    // ---------------- epilogue ----------------
    const int g = lane >> 2, tq = lane & 3;
#pragma unroll
    for (int mt = 0; mt < 4; mt++) {
#pragma unroll
        for (int nt = 0; nt < 4; nt++) {
            const int r = m0 + wm0 + mt * 16 + g;
            const int c = n0 + wn0 + nt * 8 + tq * 2;
            float v0 = acc[mt][nt][0], v1 = acc[mt][nt][1];
            float v2 = acc[mt][nt][2], v3 = acc[mt][nt][3];
            if (EPI == 0) {
                float* C = pCf + (size_t)bz * sC;
                *(float2*)&C[(size_t)r * ldc + c] = make_float2(v0, v1);
                *(float2*)&C[(size_t)(r + 8) * ldc + c] = make_float2(v2, v3);
            } else {
                __half* Chi = pChi + (size_t)bz * sC;
                __half h0 = __float2half_rn(v0), h1 = __float2half_rn(v1);
                __half h2 = __float2half_rn(v2), h3 = __float2half_rn(v3);
                *(__half2*)&Chi[(size_t)r * ldc + c] = __halves2half2(h0, h1);
                *(__half2*)&Chi[(size_t)(r + 8) * ldc + c] = __halves2half2(h2, h3);
                if (EPI == 1) {
                    __half* Clo = pClo + (size_t)bz * sC;
                    *(__half2*)&Clo[(size_t)r * ldc + c] =
                        __halves2half2(__float2half_rn(v0 - __half2float(h0)),
                                       __float2half_rn(v1 - __half2float(h1)));
                    *(__half2*)&Clo[(size_t)(r + 8) * ldc + c] =
                        __halves2half2(__float2half_rn(v2 - __half2float(h2)),
                                       __float2half_rn(v3 - __half2float(h3)));
                }
            }
        }
    }
}

// ---------------- masked softmax: P = softmax(where(mask,E,-1e10)/32) ----------------
__global__ void softmax_kernel(const float* __restrict__ E, const int* __restrict__ mask,
                               __half* __restrict__ P) {
    const size_t base = (size_t)blockIdx.x * Ms;
    const int tid = threadIdx.x;
    __shared__ float redm[8];
    __shared__ float reds[8];

    const float4* E4 = (const float4*)(E + base);
    const int4* M4 = (const int4*)(mask + base);

    float v[8];
    float mx = -3.4e38f;
#pragma unroll
    for (int i = 0; i < 2; i++) {
        float4 e = E4[tid * 2 + i];
        int4 mk = M4[tid * 2 + i];
        float* vv = v + i * 4;
        vv[0] = mk.x ? e.x * 0.03125f : -3.125e8f;
        vv[1] = mk.y ? e.y * 0.03125f : -3.125e8f;
        vv[2] = mk.z ? e.z * 0.03125f : -3.125e8f;
        vv[3] = mk.w ? e.w * 0.03125f : -3.125e8f;
        mx = fmaxf(mx, fmaxf(fmaxf(vv[0], vv[1]), fmaxf(vv[2], vv[3])));
    }
#pragma unroll
    for (int o = 16; o; o >>= 1) mx = fmaxf(mx, __shfl_xor_sync(0xffffffffu, mx, o));
    if ((tid & 31) == 0) redm[tid >> 5] = mx;
    __syncthreads();
    if (tid < 8) {
        float m2 = redm[tid];
#pragma unroll
        for (int o = 4; o; o >>= 1) m2 = fmaxf(m2, __shfl_xor_sync(0xffu, m2, o));
        redm[tid] = m2;
    }
    __syncthreads();
    mx = redm[0];

    float s = 0.f;
#pragma unroll
    for (int i = 0; i < 8; i++) {
        v[i] = __expf(v[i] - mx);
        s += v[i];
    }
#pragma unroll
    for (int o = 16; o; o >>= 1) s += __shfl_xor_sync(0xffffffffu, s, o);
    if ((tid & 31) == 0) reds[tid >> 5] = s;
    __syncthreads();
    if (tid < 8) {
        float s2 = reds[tid];
#pragma unroll
        for (int o = 4; o; o >>= 1) s2 += __shfl_xor_sync(0xffu, s2, o);
        reds[tid] = s2;
    }
    __syncthreads();
    const float inv = 1.0f / reds[0];
    __half2* P2 = (__half2*)(P + base);
#pragma unroll
    for (int i = 0; i < 4; i++) {
        P2[tid * 4 + i] = __halves2half2(__float2half_rn(v[2 * i] * inv),
                                         __float2half_rn(v[2 * i + 1] * inv));
    }
}

// ---------------- launch ----------------
extern "C" void kernel_launch(void* const* d_in, const int* in_sizes, int n_in,
                              void* d_out, int out_size) {
    (void)in_sizes; (void)n_in; (void)out_size;
    const float* h1 = (const float*)d_in[0];
    const float* h2 = (const float*)d_in[1];
    const int* mask = (const int*)d_in[2];
    const float* Wq = (const float*)d_in[3];
    const float* Wk = (const float*)d_in[4];
    const float* Wv = (const float*)d_in[5];
    float* out = (float*)d_out;

    __half *h1h, *h2h, *h2l, *Wqh, *Wql, *Wkh, *Wkl, *Wvh;
    __half *Qh, *Kh, *Vth, *P;
    float* E;
    cudaGetSymbolAddress((void**)&h1h, g_h1h);
    cudaGetSymbolAddress((void**)&h2h, g_h2h);
    cudaGetSymbolAddress((void**)&h2l, g_h2l);
    cudaGetSymbolAddress((void**)&Wqh, g_Wqh);
    cudaGetSymbolAddress((void**)&Wql, g_Wql);
    cudaGetSymbolAddress((void**)&Wkh, g_Wkh);
    cudaGetSymbolAddress((void**)&Wkl, g_Wkl);
    cudaGetSymbolAddress((void**)&Wvh, g_Wvh);
    cudaGetSymbolAddress((void**)&Qh, g_Qh);
    cudaGetSymbolAddress((void**)&Kh, g_Kh);
    cudaGetSymbolAddress((void**)&Vth, g_Vth);
    cudaGetSymbolAddress((void**)&E, g_E);
    cudaGetSymbolAddress((void**)&P, g_P);

    const int smem_nt2 = 3 * BM * LDS * 2 * NSTAGE;   // 110592 B -> 2 CTAs/SM
    const int smem_nt1 = 2 * BM * LDS * 2 * NSTAGE;   //  73728 B -> 2 CTAs/SM
    cudaFuncSetAttribute((const void*)gemm_kernel<2, 2>,
                         cudaFuncAttributeMaxDynamicSharedMemorySize, smem_nt2);
    cudaFuncSetAttribute((const void*)gemm_kernel<0, 1>,
                         cudaFuncAttributeMaxDynamicSharedMemorySize, smem_nt1);

    // fused split, single launch
    split_all_kernel<<<(R4v + 255) / 256, 256>>>(
        (const float4*)h1, (const float4*)h2, (const float4*)Wq, (const float4*)Wk,
        (const float4*)Wv,
        (__half2*)h1h, (__half2*)h2h, (__half2*)h2l,
        (__half2*)Wqh, (__half2*)Wql, (__half2*)Wkh, (__half2*)Wkl,
        (__half2*)Wvh);

    // Qh = h1h * (Wqh+Wql)^T  (16384 x 1024 x 1024), fp16-hi epilogue
    gemm_kernel<2, 2><<<dim3(Hh / BN, (Bz * Ns) / BM, 1), 256, smem_nt2>>>(
        h1h, Wqh, Wql, nullptr, Qh, nullptr, Dd, Dd, Dd, Hh, 0, 0, 0);
    // Kh = h2h * (Wkh+Wkl)^T, fp16-hi epilogue
    gemm_kernel<2, 2><<<dim3(Hh / BN, (Bz * Ms) / BM, 1), 256, smem_nt2>>>(
        h2h, Wkh, Wkl, nullptr, Kh, nullptr, Dd, Dd, Dd, Hh, 0, 0, 0);
    // Vth[b] = Wvh * (h2h+h2l)[b]^T, fp16-hi epilogue
    gemm_kernel<2, 2><<<dim3(Ms / BN, Oo / BM, Bz), 256, smem_nt2>>>(
        Wvh, h2h, h2l, nullptr, Vth, nullptr, Dd, Dd, Dd, Ms,
        0, (long long)Ms * Dd, (long long)Oo * Ms);
    // E[b] = Qh[b] * Kh[b]^T (2048 x 2048 x 1024), 1-term, fp32
    gemm_kernel<0, 1><<<dim3(Ms / BN, Ns / BM, Bz), 256, smem_nt1>>>(
        Qh, Kh, nullptr, E, nullptr, nullptr, Hh, Hh, Hh, Ms,
        (long long)Ns * Hh, (long long)Ms * Hh, (long long)Ns * Ms);
    // masked softmax -> P (fp16)
    softmax_kernel<<<Bz * Ns, 256>>>(E, mask, P);
    // out[b] = P[b] * Vth[b]^T (2048 x 1024 x 2048), 1-term, fp32
    gemm_kernel<0, 1><<<dim3(Oo / BN, Ns / BM, Bz), 256, smem_nt1>>>(
        P, Vth, nullptr, out, nullptr, nullptr, Ms, Ms, Ms, Oo,
        (long long)Ns * Ms, (long long)Oo * Ms, (long long)Ns * Oo);
}

// round 12
// speedup vs baseline: 2.4954x; 1.1793x over previous
#include <cuda_runtime.h>
#include <cuda_fp16.h>
#include <cstdint>

#define Bz 8
#define Ns 2048
#define Ms 2048
#define Dd 1024
#define Hh 1024
#define Oo 1024

#define BM 128
#define BN 128
#define BK 64
#define LDS 72        // padded row stride in halves (144B; conflict-free ldmatrix)
#define NSTAGE 2

// ---------------- device scratch ----------------
__device__ __half g_h1h[Bz * Ns * Dd];
__device__ __half g_h2h[Bz * Ms * Dd];
__device__ __half g_Wqh[Hh * Dd];
__device__ __half g_Wql[Hh * Dd];
__device__ __half g_Wkh[Hh * Dd];
__device__ __half g_Wvh[Oo * Dd];
__device__ __half g_Qh[Bz * Ns * Hh];
__device__ __half g_Kh[Bz * Ms * Hh];
__device__ __half g_Vth[Bz * Oo * Ms];   // V transposed: [b][o][m]
__device__ float  g_E[(size_t)Bz * Ns * Ms];
__device__ __half g_P[(size_t)Bz * Ns * Ms];

// ---------------- fused fp32 -> fp16 split ----------------
// h1 -> hi; h2 -> hi; Wq -> hi+lo; Wk -> hi; Wv -> hi
#define R0 4194304    // h1 float4 count
#define R1 8388608    // + h2
#define R2q 8650752   // + Wq
#define R3k 8912896   // + Wk
#define R4v 9175040   // + Wv

__global__ void split_all_kernel(const float4* __restrict__ h1, const float4* __restrict__ h2,
                                 const float4* __restrict__ Wq, const float4* __restrict__ Wk,
                                 const float4* __restrict__ Wv,
                                 __half2* __restrict__ h1h, __half2* __restrict__ h2h,
                                 __half2* __restrict__ Wqh, __half2* __restrict__ Wql,
                                 __half2* __restrict__ Wkh, __half2* __restrict__ Wvh) {
    int i = blockIdx.x * blockDim.x + threadIdx.x;
    const float4* src;
    __half2 *hi, *lo = nullptr;
    int j;
    if (i < R0)       { src = h1; hi = h1h; j = i; }
    else if (i < R1)  { src = h2; hi = h2h; j = i - R0; }
    else if (i < R2q) { src = Wq; hi = Wqh; lo = Wql; j = i - R1; }
    else if (i < R3k) { src = Wk; hi = Wkh; j = i - R2q; }
    else if (i < R4v) { src = Wv; hi = Wvh; j = i - R3k; }
    else return;
    float4 v = src[j];
    __half a = __float2half_rn(v.x), b = __float2half_rn(v.y);
    __half c = __float2half_rn(v.z), d = __float2half_rn(v.w);
    hi[2 * j + 0] = __halves2half2(a, b);
    hi[2 * j + 1] = __halves2half2(c, d);
    if (lo) {
        lo[2 * j + 0] = __halves2half2(__float2half_rn(v.x - __half2float(a)),
                                       __float2half_rn(v.y - __half2float(b)));
        lo[2 * j + 1] = __halves2half2(__float2half_rn(v.z - __half2float(c)),
                                       __float2half_rn(v.w - __half2float(d)));
    }
}

// ---------------- PTX helpers ----------------
__device__ __forceinline__ void ldsm4(uint32_t& r0, uint32_t& r1, uint32_t& r2, uint32_t& r3,
                                      uint32_t addr) {
    asm volatile("ldmatrix.sync.aligned.m8n8.x4.shared.b16 {%0,%1,%2,%3}, [%4];"
                 : "=r"(r0), "=r"(r1), "=r"(r2), "=r"(r3)
                 : "r"(addr));
}

__device__ __forceinline__ void mma16816(float* c, const uint32_t* a, uint32_t b0, uint32_t b1) {
    asm volatile("mma.sync.aligned.m16n8k16.row.col.f32.f16.f16.f32 "
                 "{%0,%1,%2,%3}, {%4,%5,%6,%7}, {%8,%9}, {%0,%1,%2,%3};"
                 : "+f"(c[0]), "+f"(c[1]), "+f"(c[2]), "+f"(c[3])
                 : "r"(a[0]), "r"(a[1]), "r"(a[2]), "r"(a[3]), "r"(b0), "r"(b1));
}

__device__ __forceinline__ void cp16(uint32_t dst, const void* src) {
    asm volatile("cp.async.cg.shared.global [%0], [%1], 16;" :: "r"(dst), "l"(src));
}
__device__ __forceinline__ void cp_commit() { asm volatile("cp.async.commit_group;"); }
template <int N>
__device__ __forceinline__ void cp_wait() { asm volatile("cp.async.wait_group %0;" :: "n"(N)); }

// ---------------- double-buffered split GEMM, BK=64, 2 CTAs/SM ----------------
// NT=2: C = Ah*Bh^T + Ah*Bl^T.   NT=1: C = Ah*Bh^T.
// A: [Mdim x K] row-major, B: [Ndim x K] row-major (both K-contiguous).
// EPI 0: fp32 C.  EPI 2: fp16 hi only.
template <int EPI, int NT>
__global__ void __launch_bounds__(256, 2)
gemm_kernel(const __half* __restrict__ pAh,
            const __half* __restrict__ pBh, const __half* __restrict__ pBl,
            float* __restrict__ pCf, __half* __restrict__ pChi,
            int Kdim, int lda, int ldb, int ldc,
            long long sA, long long sB, long long sC) {
    extern __shared__ __align__(16) __half sm[];
    constexpr int TILE = BM * LDS;                          // halves per tile (9216)
    constexpr uint32_t STAGE_B = (NT + 1) * TILE * 2;       // Ah, Bh[, Bl]

    const int tid = threadIdx.x;
    const int bz = blockIdx.z;
    const int m0 = blockIdx.y * BM;
    const int n0 = blockIdx.x * BN;

    const __half* gAh = pAh + (size_t)bz * sA + (size_t)m0 * lda;
    const __half* gBh = pBh + (size_t)bz * sB + (size_t)n0 * ldb;
    const __half* gBl = (NT == 2) ? (pBl + (size_t)bz * sB + (size_t)n0 * ldb) : gBh;

    const uint32_t smbase = (uint32_t)__cvta_generic_to_shared(sm);

    const int lane = tid & 31;
    const int wid = tid >> 5;
    const int wm0 = (wid & 1) * 64;
    const int wn0 = (wid >> 1) * 32;

    const uint32_t aoff =
        (uint32_t)(((wm0 + (lane & 15)) * LDS + ((lane >> 4) & 1) * 8) * 2);
    const uint32_t boff =
        (uint32_t)(((wn0 + (lane & 7) + ((lane >> 4) & 1) * 8) * LDS + ((lane >> 3) & 1) * 8) * 2);

    float acc[4][4][4];
#pragma unroll
    for (int i = 0; i < 4; i++)
#pragma unroll
        for (int j = 0; j < 4; j++)
#pragma unroll
            for (int k = 0; k < 4; k++) acc[i][j][k] = 0.f;

    // ---- stage load (cp.async): 4 chunks per thread per tile ----
    auto issue = [&](int st, int kt) {
        const uint32_t b = smbase + (uint32_t)st * STAGE_B;
#pragma unroll
        for (int i = 0; i < 4; i++) {
            const int q = i * 256 + tid;
            const int r = q >> 3, c = (q & 7) * 8;   // row 0..127, col chunk (halves)
            const uint32_t d = b + (uint32_t)((r * LDS + c) * 2);
            cp16(d, gAh + (size_t)r * lda + kt + c);
            cp16(d + TILE * 2, gBh + (size_t)r * ldb + kt + c);
            if constexpr (NT == 2)
                cp16(d + 2 * TILE * 2, gBl + (size_t)r * ldb + kt + c);
        }
        cp_commit();
    };

    // ---- stage compute: 4 kk steps of K=16 ----
    auto compute = [&](int st) {
        const uint32_t b = smbase + (uint32_t)st * STAGE_B;
        const uint32_t uA = b + aoff;
        const uint32_t uBh = b + TILE * 2 + boff;
        const uint32_t uBl = b + 2 * TILE * 2 + boff;
#pragma unroll
        for (int kk = 0; kk < 4; kk++) {
            uint32_t fAh[4][4], fB[4][2];
#pragma unroll
            for (int mt = 0; mt < 4; mt++)
                ldsm4(fAh[mt][0], fAh[mt][1], fAh[mt][2], fAh[mt][3],
                      uA + mt * (16 * LDS * 2) + kk * 32);
#pragma unroll
            for (int p = 0; p < 2; p++) {
                uint32_t r0, r1, r2, r3;
                ldsm4(r0, r1, r2, r3, uBh + p * (16 * LDS * 2) + kk * 32);
                fB[2 * p][0] = r0; fB[2 * p][1] = r1;
                fB[2 * p + 1][0] = r2; fB[2 * p + 1][1] = r3;
            }
#pragma unroll
            for (int mt = 0; mt < 4; mt++)
#pragma unroll
                for (int nt = 0; nt < 4; nt++)
                    mma16816(acc[mt][nt], fAh[mt], fB[nt][0], fB[nt][1]);
            if constexpr (NT == 2) {
#pragma unroll
                for (int p = 0; p < 2; p++) {
                    uint32_t r0, r1, r2, r3;
                    ldsm4(r0, r1, r2, r3, uBl + p * (16 * LDS * 2) + kk * 32);
                    fB[2 * p][0] = r0; fB[2 * p][1] = r1;
                    fB[2 * p + 1][0] = r2; fB[2 * p + 1][1] = r3;
                }
#pragma unroll
                for (int mt = 0; mt < 4; mt++)
#pragma unroll
                    for (int nt = 0; nt < 4; nt++)
                        mma16816(acc[mt][nt], fAh[mt], fB[nt][0], fB[nt][1]);
            }
        }
    };

    // ---- double-buffer pipeline (KT = Kdim/64) ----
    const int KT = Kdim / BK;
    issue(0, 0);
    int cur = 0;
    for (int t = 0; t < KT; t++) {
        cp_wait<0>();
        __syncthreads();
        if (t + 1 < KT) issue(1 - cur, (t + 1) * BK);
        compute(cur);
        cur ^= 1;
    }

    // ---------------- epilogue ----------------
    const int g = lane >> 2, tq = lane & 3;
#pragma unroll
    for (int mt = 0; mt < 4; mt++) {
#pragma unroll
        for (int nt = 0; nt < 4; nt++) {
            const int r = m0 + wm0 + mt * 16 + g;
            const int c = n0 + wn0 + nt * 8 + tq * 2;
            float v0 = acc[mt][nt][0], v1 = acc[mt][nt][1];
            float v2 = acc[mt][nt][2], v3 = acc[mt][nt][3];
            if (EPI == 0) {
                float* C = pCf + (size_t)bz * sC;
                *(float2*)&C[(size_t)r * ldc + c] = make_float2(v0, v1);
                *(float2*)&C[(size_t)(r + 8) * ldc + c] = make_float2(v2, v3);
            } else {
                __half* Chi = pChi + (size_t)bz * sC;
                *(__half2*)&Chi[(size_t)r * ldc + c] =
                    __halves2half2(__float2half_rn(v0), __float2half_rn(v1));
                *(__half2*)&Chi[(size_t)(r + 8) * ldc + c] =
                    __halves2half2(__float2half_rn(v2), __float2half_rn(v3));
            }
        }
    }
}

// ---------------- masked softmax: P = softmax(where(mask,E,-1e10)/32) ----------------
__global__ void softmax_kernel(const float* __restrict__ E, const int* __restrict__ mask,
                               __half* __restrict__ P) {
    const size_t base = (size_t)blockIdx.x * Ms;
    const int tid = threadIdx.x;
    __shared__ float redm[8];
    __shared__ float reds[8];

    const float4* E4 = (const float4*)(E + base);
    const int4* M4 = (const int4*)(mask + base);

    float v[8];
    float mx = -3.4e38f;
#pragma unroll
    for (int i = 0; i < 2; i++) {
        float4 e = E4[tid * 2 + i];
        int4 mk = M4[tid * 2 + i];
        float* vv = v + i * 4;
        vv[0] = mk.x ? e.x * 0.03125f : -3.125e8f;
        vv[1] = mk.y ? e.y * 0.03125f : -3.125e8f;
        vv[2] = mk.z ? e.z * 0.03125f : -3.125e8f;
        vv[3] = mk.w ? e.w * 0.03125f : -3.125e8f;
        mx = fmaxf(mx, fmaxf(fmaxf(vv[0], vv[1]), fmaxf(vv[2], vv[3])));
    }
#pragma unroll
    for (int o = 16; o; o >>= 1) mx = fmaxf(mx, __shfl_xor_sync(0xffffffffu, mx, o));
    if ((tid & 31) == 0) redm[tid >> 5] = mx;
    __syncthreads();
    if (tid < 8) {
        float m2 = redm[tid];
#pragma unroll
        for (int o = 4; o; o >>= 1) m2 = fmaxf(m2, __shfl_xor_sync(0xffu, m2, o));
        redm[tid] = m2;
    }
    __syncthreads();
    mx = redm[0];

    float s = 0.f;
#pragma unroll
    for (int i = 0; i < 8; i++) {
        v[i] = __expf(v[i] - mx);
        s += v[i];
    }
#pragma unroll
    for (int o = 16; o; o >>= 1) s += __shfl_xor_sync(0xffffffffu, s, o);
    if ((tid & 31) == 0) reds[tid >> 5] = s;
    __syncthreads();
    if (tid < 8) {
        float s2 = reds[tid];
#pragma unroll
        for (int o = 4; o; o >>= 1) s2 += __shfl_xor_sync(0xffu, s2, o);
        reds[tid] = s2;
    }
    __syncthreads();
    const float inv = 1.0f / reds[0];
    __half2* P2 = (__half2*)(P + base);
#pragma unroll
    for (int i = 0; i < 4; i++) {
        P2[tid * 4 + i] = __halves2half2(__float2half_rn(v[2 * i] * inv),
                                         __float2half_rn(v[2 * i + 1] * inv));
    }
}

// ---------------- launch ----------------
extern "C" void kernel_launch(void* const* d_in, const int* in_sizes, int n_in,
                              void* d_out, int out_size) {
    (void)in_sizes; (void)n_in; (void)out_size;
    const float* h1 = (const float*)d_in[0];
    const float* h2 = (const float*)d_in[1];
    const int* mask = (const int*)d_in[2];
    const float* Wq = (const float*)d_in[3];
    const float* Wk = (const float*)d_in[4];
    const float* Wv = (const float*)d_in[5];
    float* out = (float*)d_out;

    __half *h1h, *h2h, *Wqh, *Wql, *Wkh, *Wvh;
    __half *Qh, *Kh, *Vth, *P;
    float* E;
    cudaGetSymbolAddress((void**)&h1h, g_h1h);
    cudaGetSymbolAddress((void**)&h2h, g_h2h);
    cudaGetSymbolAddress((void**)&Wqh, g_Wqh);
    cudaGetSymbolAddress((void**)&Wql, g_Wql);
    cudaGetSymbolAddress((void**)&Wkh, g_Wkh);
    cudaGetSymbolAddress((void**)&Wvh, g_Wvh);
    cudaGetSymbolAddress((void**)&Qh, g_Qh);
    cudaGetSymbolAddress((void**)&Kh, g_Kh);
    cudaGetSymbolAddress((void**)&Vth, g_Vth);
    cudaGetSymbolAddress((void**)&E, g_E);
    cudaGetSymbolAddress((void**)&P, g_P);

    const int smem_nt2 = 3 * BM * LDS * 2 * NSTAGE;   // 110592 B -> 2 CTAs/SM
    const int smem_nt1 = 2 * BM * LDS * 2 * NSTAGE;   //  73728 B -> 2 CTAs/SM
    cudaFuncSetAttribute((const void*)gemm_kernel<2, 2>,
                         cudaFuncAttributeMaxDynamicSharedMemorySize, smem_nt2);
    cudaFuncSetAttribute((const void*)gemm_kernel<2, 1>,
                         cudaFuncAttributeMaxDynamicSharedMemorySize, smem_nt1);
    cudaFuncSetAttribute((const void*)gemm_kernel<0, 1>,
                         cudaFuncAttributeMaxDynamicSharedMemorySize, smem_nt1);

    // fused split, single launch
    split_all_kernel<<<(R4v + 255) / 256, 256>>>(
        (const float4*)h1, (const float4*)h2, (const float4*)Wq, (const float4*)Wk,
        (const float4*)Wv,
        (__half2*)h1h, (__half2*)h2h,
        (__half2*)Wqh, (__half2*)Wql, (__half2*)Wkh, (__half2*)Wvh);

    // Qh = h1h * (Wqh+Wql)^T  (16384 x 1024 x 1024), 2-term, fp16-hi epilogue
    gemm_kernel<2, 2><<<dim3(Hh / BN, (Bz * Ns) / BM, 1), 256, smem_nt2>>>(
        h1h, Wqh, Wql, nullptr, Qh, Dd, Dd, Dd, Hh, 0, 0, 0);
    // Kh = h2h * Wkh^T, 1-term, fp16-hi epilogue
    gemm_kernel<2, 1><<<dim3(Hh / BN, (Bz * Ms) / BM, 1), 256, smem_nt1>>>(
        h2h, Wkh, nullptr, nullptr, Kh, Dd, Dd, Dd, Hh, 0, 0, 0);
    // Vth[b] = Wvh * h2h[b]^T, 1-term, fp16-hi epilogue
    gemm_kernel<2, 1><<<dim3(Ms / BN, Oo / BM, Bz), 256, smem_nt1>>>(
        Wvh, h2h, nullptr, nullptr, Vth, Dd, Dd, Dd, Ms,
        0, (long long)Ms * Dd, (long long)Oo * Ms);
    // E[b] = Qh[b] * Kh[b]^T (2048 x 2048 x 1024), 1-term, fp32
    gemm_kernel<0, 1><<<dim3(Ms / BN, Ns / BM, Bz), 256, smem_nt1>>>(
        Qh, Kh, nullptr, E, nullptr, Hh, Hh, Hh, Ms,
        (long long)Ns * Hh, (long long)Ms * Hh, (long long)Ns * Ms);
    // masked softmax -> P (fp16)
    softmax_kernel<<<Bz * Ns, 256>>>(E, mask, P);
    // out[b] = P[b] * Vth[b]^T (2048 x 1024 x 2048), 1-term, fp32
    gemm_kernel<0, 1><<<dim3(Oo / BN, Ns / BM, Bz), 256, smem_nt1>>>(
        P, Vth, nullptr, out, nullptr, Ms, Ms, Ms, Oo,
        (long long)Ns * Ms, (long long)Oo * Ms, (long long)Ns * Oo);
}

// round 14
// speedup vs baseline: 2.7231x; 1.0913x over previous
#include <cuda_runtime.h>
#include <cuda_fp16.h>
#include <cstdint>

#define Bz 8
#define Ns 2048
#define Ms 2048
#define Dd 1024
#define Hh 1024
#define Oo 1024

#define BM 128
#define BN 128
#define BK 64
#define LDS 72        // padded row stride in halves (144B; conflict-free ldmatrix)
#define NSTAGE 2

// ---------------- device scratch ----------------
__device__ __half g_h1h[Bz * Ns * Dd];
__device__ __half g_h2h[Bz * Ms * Dd];
__device__ __half g_Wqh[Hh * Dd];
__device__ __half g_Wkh[Hh * Dd];
__device__ __half g_Wvh[Oo * Dd];
__device__ __half g_Qh[Bz * Ns * Hh];
__device__ __half g_Kh[Bz * Ms * Hh];
__device__ __half g_Vth[Bz * Oo * Ms];   // V transposed: [b][o][m]
__device__ float  g_E[(size_t)Bz * Ns * Ms];
__device__ __half g_P[(size_t)Bz * Ns * Ms];

// ---------------- fused fp32 -> fp16 convert (hi only, all tensors) ----------------
#define R0 4194304    // h1 float4 count
#define R1 8388608    // + h2
#define R2q 8650752   // + Wq
#define R3k 8912896   // + Wk
#define R4v 9175040   // + Wv

__global__ void split_all_kernel(const float4* __restrict__ h1, const float4* __restrict__ h2,
                                 const float4* __restrict__ Wq, const float4* __restrict__ Wk,
                                 const float4* __restrict__ Wv,
                                 __half2* __restrict__ h1h, __half2* __restrict__ h2h,
                                 __half2* __restrict__ Wqh, __half2* __restrict__ Wkh,
                                 __half2* __restrict__ Wvh) {
    int i = blockIdx.x * blockDim.x + threadIdx.x;
    const float4* src;
    __half2* hi;
    int j;
    if (i < R0)       { src = h1; hi = h1h; j = i; }
    else if (i < R1)  { src = h2; hi = h2h; j = i - R0; }
    else if (i < R2q) { src = Wq; hi = Wqh; j = i - R1; }
    else if (i < R3k) { src = Wk; hi = Wkh; j = i - R2q; }
    else if (i < R4v) { src = Wv; hi = Wvh; j = i - R3k; }
    else return;
    float4 v = src[j];
    hi[2 * j + 0] = __halves2half2(__float2half_rn(v.x), __float2half_rn(v.y));
    hi[2 * j + 1] = __halves2half2(__float2half_rn(v.z), __float2half_rn(v.w));
}

// ---------------- PTX helpers ----------------
__device__ __forceinline__ void ldsm4(uint32_t& r0, uint32_t& r1, uint32_t& r2, uint32_t& r3,
                                      uint32_t addr) {
    asm volatile("ldmatrix.sync.aligned.m8n8.x4.shared.b16 {%0,%1,%2,%3}, [%4];"
                 : "=r"(r0), "=r"(r1), "=r"(r2), "=r"(r3)
                 : "r"(addr));
}

__device__ __forceinline__ void mma16816(float* c, const uint32_t* a, uint32_t b0, uint32_t b1) {
    asm volatile("mma.sync.aligned.m16n8k16.row.col.f32.f16.f16.f32 "
                 "{%0,%1,%2,%3}, {%4,%5,%6,%7}, {%8,%9}, {%0,%1,%2,%3};"
                 : "+f"(c[0]), "+f"(c[1]), "+f"(c[2]), "+f"(c[3])
                 : "r"(a[0]), "r"(a[1]), "r"(a[2]), "r"(a[3]), "r"(b0), "r"(b1));
}

__device__ __forceinline__ void cp16(uint32_t dst, const void* src) {
    asm volatile("cp.async.cg.shared.global [%0], [%1], 16;" :: "r"(dst), "l"(src));
}
__device__ __forceinline__ void cp_commit() { asm volatile("cp.async.commit_group;"); }
template <int N>
__device__ __forceinline__ void cp_wait() { asm volatile("cp.async.wait_group %0;" :: "n"(N)); }

// ---------------- double-buffered fp16 GEMM, BK=64, 2 CTAs/SM ----------------
// C = A*B^T.  A: [Mdim x K] row-major, B: [Ndim x K] row-major (K-contiguous).
// EPI 0: fp32 C.  EPI 2: fp16 C.
template <int EPI>
__global__ void __launch_bounds__(256, 2)
gemm_kernel(const __half* __restrict__ pA, const __half* __restrict__ pB,
            float* __restrict__ pCf, __half* __restrict__ pCh,
            int Kdim, int lda, int ldb, int ldc,
            long long sA, long long sB, long long sC) {
    extern __shared__ __align__(16) __half sm[];
    constexpr int TILE = BM * LDS;                 // halves per tile (9216)
    constexpr uint32_t STAGE_B = 2 * TILE * 2;     // A, B = 36864 B

    const int tid = threadIdx.x;
    const int bz = blockIdx.z;
    const int m0 = blockIdx.y * BM;
    const int n0 = blockIdx.x * BN;

    const __half* gA = pA + (size_t)bz * sA + (size_t)m0 * lda;
    const __half* gB = pB + (size_t)bz * sB + (size_t)n0 * ldb;

    const uint32_t smbase = (uint32_t)__cvta_generic_to_shared(sm);

    const int lane = tid & 31;
    const int wid = tid >> 5;
    const int wm0 = (wid & 1) * 64;
    const int wn0 = (wid >> 1) * 32;

    const uint32_t aoff =
        (uint32_t)(((wm0 + (lane & 15)) * LDS + ((lane >> 4) & 1) * 8) * 2);
    const uint32_t boff =
        (uint32_t)(((wn0 + (lane & 7) + ((lane >> 4) & 1) * 8) * LDS + ((lane >> 3) & 1) * 8) * 2);

    float acc[4][4][4];
#pragma unroll
    for (int i = 0; i < 4; i++)
#pragma unroll
        for (int j = 0; j < 4; j++)
#pragma unroll
            for (int k = 0; k < 4; k++) acc[i][j][k] = 0.f;

    // ---- stage load (cp.async): 4 chunks per thread per tile ----
    auto issue = [&](int st, int kt) {
        const uint32_t b = smbase + (uint32_t)st * STAGE_B;
#pragma unroll
        for (int i = 0; i < 4; i++) {
            const int q = i * 256 + tid;
            const int r = q >> 3, c = (q & 7) * 8;   // row 0..127, col chunk (halves)
            const uint32_t d = b + (uint32_t)((r * LDS + c) * 2);
            cp16(d, gA + (size_t)r * lda + kt + c);
            cp16(d + TILE * 2, gB + (size_t)r * ldb + kt + c);
        }
        cp_commit();
    };

    // ---- stage compute: 4 kk steps of K=16 ----
    auto compute = [&](int st) {
        const uint32_t b = smbase + (uint32_t)st * STAGE_B;
        const uint32_t uA = b + aoff;
        const uint32_t uB = b + TILE * 2 + boff;
#pragma unroll
        for (int kk = 0; kk < 4; kk++) {
            uint32_t fA[4][4], fB[4][2];
#pragma unroll
            for (int mt = 0; mt < 4; mt++)
                ldsm4(fA[mt][0], fA[mt][1], fA[mt][2], fA[mt][3],
                      uA + mt * (16 * LDS * 2) + kk * 32);
#pragma unroll
            for (int p = 0; p < 2; p++) {
                uint32_t r0, r1, r2, r3;
                ldsm4(r0, r1, r2, r3, uB + p * (16 * LDS * 2) + kk * 32);
                fB[2 * p][0] = r0; fB[2 * p][1] = r1;
                fB[2 * p + 1][0] = r2; fB[2 * p + 1][1] = r3;
            }
#pragma unroll
            for (int mt = 0; mt < 4; mt++)
#pragma unroll
                for (int nt = 0; nt < 4; nt++)
                    mma16816(acc[mt][nt], fA[mt], fB[nt][0], fB[nt][1]);
        }
    };

    // ---- double-buffer pipeline (KT = Kdim/64) ----
    const int KT = Kdim / BK;
    issue(0, 0);
    int cur = 0;
    for (int t = 0; t < KT; t++) {
        cp_wait<0>();
        __syncthreads();
        if (t + 1 < KT) issue(1 - cur, (t + 1) * BK);
        compute(cur);
        cur ^= 1;
    }

    // ---------------- epilogue ----------------
    const int g = lane >> 2, tq = lane & 3;
#pragma unroll
    for (int mt = 0; mt < 4; mt++) {
#pragma unroll
        for (int nt = 0; nt < 4; nt++) {
            const int r = m0 + wm0 + mt * 16 + g;
            const int c = n0 + wn0 + nt * 8 + tq * 2;
            float v0 = acc[mt][nt][0], v1 = acc[mt][nt][1];
            float v2 = acc[mt][nt][2], v3 = acc[mt][nt][3];
            if (EPI == 0) {
                float* C = pCf + (size_t)bz * sC;
                *(float2*)&C[(size_t)r * ldc + c] = make_float2(v0, v1);
                *(float2*)&C[(size_t)(r + 8) * ldc + c] = make_float2(v2, v3);
            } else {
                __half* Ch = pCh + (size_t)bz * sC;
                *(__half2*)&Ch[(size_t)r * ldc + c] =
                    __halves2half2(__float2half_rn(v0), __float2half_rn(v1));
                *(__half2*)&Ch[(size_t)(r + 8) * ldc + c] =
                    __halves2half2(__float2half_rn(v2), __float2half_rn(v3));
            }
        }
    }
}

// ---------------- masked softmax: P = softmax(where(mask,E,-1e10)/32) ----------------
__global__ void softmax_kernel(const float* __restrict__ E, const int* __restrict__ mask,
                               __half* __restrict__ P) {
    const size_t base = (size_t)blockIdx.x * Ms;
    const int tid = threadIdx.x;
    __shared__ float redm[8];
    __shared__ float reds[8];

    const float4* E4 = (const float4*)(E + base);
    const int4* M4 = (const int4*)(mask + base);

    float v[8];
    float mx = -3.4e38f;
#pragma unroll
    for (int i = 0; i < 2; i++) {
        float4 e = E4[tid * 2 + i];
        int4 mk = M4[tid * 2 + i];
        float* vv = v + i * 4;
        vv[0] = mk.x ? e.x * 0.03125f : -3.125e8f;
        vv[1] = mk.y ? e.y * 0.03125f : -3.125e8f;
        vv[2] = mk.z ? e.z * 0.03125f : -3.125e8f;
        vv[3] = mk.w ? e.w * 0.03125f : -3.125e8f;
        mx = fmaxf(mx, fmaxf(fmaxf(vv[0], vv[1]), fmaxf(vv[2], vv[3])));
    }
#pragma unroll
    for (int o = 16; o; o >>= 1) mx = fmaxf(mx, __shfl_xor_sync(0xffffffffu, mx, o));
    if ((tid & 31) == 0) redm[tid >> 5] = mx;
    __syncthreads();
    if (tid < 8) {
        float m2 = redm[tid];
#pragma unroll
        for (int o = 4; o; o >>= 1) m2 = fmaxf(m2, __shfl_xor_sync(0xffu, m2, o));
        redm[tid] = m2;
    }
    __syncthreads();
    mx = redm[0];

    float s = 0.f;
#pragma unroll
    for (int i = 0; i < 8; i++) {
        v[i] = __expf(v[i] - mx);
        s += v[i];
    }
#pragma unroll
    for (int o = 16; o; o >>= 1) s += __shfl_xor_sync(0xffffffffu, s, o);
    if ((tid & 31) == 0) reds[tid >> 5] = s;
    __syncthreads();
    if (tid < 8) {
        float s2 = reds[tid];
#pragma unroll
        for (int o = 4; o; o >>= 1) s2 += __shfl_xor_sync(0xffu, s2, o);
        reds[tid] = s2;
    }
    __syncthreads();
    const float inv = 1.0f / reds[0];
    __half2* P2 = (__half2*)(P + base);
#pragma unroll
    for (int i = 0; i < 4; i++) {
        P2[tid * 4 + i] = __halves2half2(__float2half_rn(v[2 * i] * inv),
                                         __float2half_rn(v[2 * i + 1] * inv));
    }
}

// ---------------- launch ----------------
extern "C" void kernel_launch(void* const* d_in, const int* in_sizes, int n_in,
                              void* d_out, int out_size) {
    (void)in_sizes; (void)n_in; (void)out_size;
    const float* h1 = (const float*)d_in[0];
    const float* h2 = (const float*)d_in[1];
    const int* mask = (const int*)d_in[2];
    const float* Wq = (const float*)d_in[3];
    const float* Wk = (const float*)d_in[4];
    const float* Wv = (const float*)d_in[5];
    float* out = (float*)d_out;

    __half *h1h, *h2h, *Wqh, *Wkh, *Wvh;
    __half *Qh, *Kh, *Vth, *P;
    float* E;
    cudaGetSymbolAddress((void**)&h1h, g_h1h);
    cudaGetSymbolAddress((void**)&h2h, g_h2h);
    cudaGetSymbolAddress((void**)&Wqh, g_Wqh);
    cudaGetSymbolAddress((void**)&Wkh, g_Wkh);
    cudaGetSymbolAddress((void**)&Wvh, g_Wvh);
    cudaGetSymbolAddress((void**)&Qh, g_Qh);
    cudaGetSymbolAddress((void**)&Kh, g_Kh);
    cudaGetSymbolAddress((void**)&Vth, g_Vth);
    cudaGetSymbolAddress((void**)&E, g_E);
    cudaGetSymbolAddress((void**)&P, g_P);

    const int smem1 = 2 * BM * LDS * 2 * NSTAGE;   // 73728 B -> 2 CTAs/SM
    cudaFuncSetAttribute((const void*)gemm_kernel<0>,
                         cudaFuncAttributeMaxDynamicSharedMemorySize, smem1);
    cudaFuncSetAttribute((const void*)gemm_kernel<2>,
                         cudaFuncAttributeMaxDynamicSharedMemorySize, smem1);

    // fused fp32->fp16 convert, single launch
    split_all_kernel<<<(R4v + 255) / 256, 256>>>(
        (const float4*)h1, (const float4*)h2, (const float4*)Wq, (const float4*)Wk,
        (const float4*)Wv,
        (__half2*)h1h, (__half2*)h2h, (__half2*)Wqh, (__half2*)Wkh, (__half2*)Wvh);

    // Qh = h1h * Wqh^T (16384 x 1024 x 1024), fp16 epilogue
    gemm_kernel<2><<<dim3(Hh / BN, (Bz * Ns) / BM, 1), 256, smem1>>>(
        h1h, Wqh, nullptr, Qh, Dd, Dd, Dd, Hh, 0, 0, 0);
    // Kh = h2h * Wkh^T, fp16 epilogue
    gemm_kernel<2><<<dim3(Hh / BN, (Bz * Ms) / BM, 1), 256, smem1>>>(
        h2h, Wkh, nullptr, Kh, Dd, Dd, Dd, Hh, 0, 0, 0);
    // Vth[b] = Wvh * h2h[b]^T, fp16 epilogue
    gemm_kernel<2><<<dim3(Ms / BN, Oo / BM, Bz), 256, smem1>>>(
        Wvh, h2h, nullptr, Vth, Dd, Dd, Dd, Ms,
        0, (long long)Ms * Dd, (long long)Oo * Ms);
    // E[b] = Qh[b] * Kh[b]^T (2048 x 2048 x 1024), fp32 epilogue
    gemm_kernel<0><<<dim3(Ms / BN, Ns / BM, Bz), 256, smem1>>>(
        Qh, Kh, E, nullptr, Hh, Hh, Hh, Ms,
        (long long)Ns * Hh, (long long)Ms * Hh, (long long)Ns * Ms);
    // masked softmax -> P (fp16)
    softmax_kernel<<<Bz * Ns, 256>>>(E, mask, P);
    // out[b] = P[b] * Vth[b]^T (2048 x 1024 x 2048), fp32 epilogue
    gemm_kernel<0><<<dim3(Oo / BN, Ns / BM, Bz), 256, smem1>>>(
        P, Vth, out, nullptr, Ms, Ms, Ms, Oo,
        (long long)Ns * Ms, (long long)Oo * Ms, (long long)Ns * Oo);
}